// round 6
// baseline (speedup 1.0000x reference)
#include <cuda_runtime.h>
#include <cuda_bf16.h>
#include <math.h>
#include <cstdint>

// Problem constants
#define Bz   8
#define Nn   4096
#define Cc   768
#define Hh   8
#define HD   96
#define M1   (Bz * Nn)          // 32768 tokens
#define BH   (Bz * Hh)          // 64
#define ROWS (BH * HD)          // 6144 rows per tensor (q or k)
#define ACHUNK 16               // split-K chunks for attention gram

// ---------------------------------------------------------------------------
// Device scratch
// ---------------------------------------------------------------------------
__device__ float g_qkv[3ull * BH * HD * Nn];                 // [t][b][h][d][n]
__device__ float g_inv[2 * ROWS];
__device__ float g_attn_part[(size_t)ACHUNK * BH * HD * HD];
__device__ float g_attn[(size_t)BH * HD * HD];
__device__ __nv_bfloat16 g_ctx_hi[(size_t)M1 * Cc];          // ctx [m][c] hi
__device__ __nv_bfloat16 g_ctx_lo[(size_t)M1 * Cc];          // ctx [m][c] lo
__device__ __nv_bfloat16 g_x_hi[(size_t)M1 * Cc];
__device__ __nv_bfloat16 g_x_lo[(size_t)M1 * Cc];
__device__ __nv_bfloat16 g_wq_hi[3 * Cc * Cc];
__device__ __nv_bfloat16 g_wq_lo[3 * Cc * Cc];
__device__ __nv_bfloat16 g_wp_hi[Cc * Cc];
__device__ __nv_bfloat16 g_wp_lo[Cc * Cc];

// ---------------------------------------------------------------------------
// PTX helpers (baseline target: mma.sync + ldmatrix + cp.async only)
// ---------------------------------------------------------------------------
#define LDSM4(R, A)                                                           \
    asm volatile("ldmatrix.sync.aligned.m8n8.x4.shared.b16 {%0,%1,%2,%3}, [%4];" \
        : "=r"((R)[0]), "=r"((R)[1]), "=r"((R)[2]), "=r"((R)[3]) : "r"(A))

#define MMA16816(C, A, B0, B1)                                                \
    asm volatile("mma.sync.aligned.m16n8k16.row.col.f32.bf16.bf16.f32 "       \
        "{%0,%1,%2,%3}, {%4,%5,%6,%7}, {%8,%9}, {%0,%1,%2,%3};"               \
        : "+f"((C)[0]), "+f"((C)[1]), "+f"((C)[2]), "+f"((C)[3])              \
        : "r"((A)[0]), "r"((A)[1]), "r"((A)[2]), "r"((A)[3]), "r"(B0), "r"(B1))

#define CP16(d, s)                                                            \
    asm volatile("cp.async.cg.shared.global [%0], [%1], 16;" :: "r"(d), "l"(s))
#define CPCOMMIT() asm volatile("cp.async.commit_group;" ::: "memory")
#define CPWAIT1()  asm volatile("cp.async.wait_group 1;" ::: "memory")
#define CPWAIT0()  asm volatile("cp.async.wait_group 0;" ::: "memory")

__device__ __forceinline__ void split2(float x, float y, uint32_t& hi, uint32_t& lo) {
    __nv_bfloat16 hx = __float2bfloat16(x), hy = __float2bfloat16(y);
    __nv_bfloat16 lx = __float2bfloat16(x - __bfloat162float(hx));
    __nv_bfloat16 ly = __float2bfloat16(y - __bfloat162float(hy));
    hi = (uint32_t)__bfloat16_as_ushort(hx) | ((uint32_t)__bfloat16_as_ushort(hy) << 16);
    lo = (uint32_t)__bfloat16_as_ushort(lx) | ((uint32_t)__bfloat16_as_ushort(ly) << 16);
}

// smem pipeline geometry (CTA tile 128M x 256N, KC=32):
//   A tile (128 rows x 64B, swizzled) = 8KB each for hi/lo
//   B tile (256 rows x 64B, swizzled) = 16KB each for hi/lo
//   stage = 48KB ; 3 stages = 144KB (dynamic)
#define A_LO_OFF  8192
#define B_HI_OFF  16384
#define B_LO_OFF  32768
#define STAGE_SZ  49152
#define NSTAGE    3
#define SMEM_GEMM (NSTAGE * STAGE_SZ)    // 147456

// ---------------------------------------------------------------------------
// Kernel 0: fp32 -> bf16 hi/lo split (prep)
// ---------------------------------------------------------------------------
__global__ __launch_bounds__(256) void split_kernel(
    const float* __restrict__ src, __nv_bfloat16* __restrict__ hi,
    __nv_bfloat16* __restrict__ lo, int n4) {
    int i = blockIdx.x * 256 + threadIdx.x;
    if (i < n4) {
        float4 v = ((const float4*)src)[i];
        uint2 h, l;
        split2(v.x, v.y, h.x, l.x);
        split2(v.z, v.w, h.y, l.y);
        ((uint2*)hi)[i] = h;
        ((uint2*)lo)[i] = l;
    }
}

// ---------------------------------------------------------------------------
// GEMM mainloop: 128x256 CTA tile, K-step 32, 3-stage cp.async pipeline,
// ONE __syncthreads per iteration. 8 warps as 2M x 4N (warp tile 64x64),
// 3-pass hi/lo bf16 MMA.
// Swizzle: smem offset(r, chunk) = r*64 + ((chunk ^ ((r>>1)&3)) << 4)
// ---------------------------------------------------------------------------
struct GemmCtx {
    const __nv_bfloat16 *Ahi, *Alo, *Bhi, *Blo;   // row-major [*, Cc]
    size_t arow, brow;                             // starting rows
};

__device__ __forceinline__ void gemm_mainloop(
    char* sm, const GemmCtx& g, float acc[4][8][4]) {
    const int tid = threadIdx.x, l = tid & 31, w = tid >> 5;
    const int wm = w & 1, wn = w >> 1;
    const uint32_t sb = (uint32_t)__cvta_generic_to_shared(sm);

    // A producer: row = tid>>1 (0..127), chunks pc0, pc0+1
    const int apr = tid >> 1, apc0 = (tid & 1) * 2;
    const int arx = (apr >> 1) & 3;
    const uint32_t poA0 = (uint32_t)(apr * 64 + ((apc0 ^ arx) << 4));
    const uint32_t poA1 = (uint32_t)(apr * 64 + (((apc0 + 1) ^ arx) << 4));
    const size_t asrc = (g.arow + apr) * Cc + apc0 * 8;

    // B producer: row = tid (0..255), chunks 0..3
    const int bpr = tid;
    const int brx = (bpr >> 1) & 3;
    uint32_t poB[4];
#pragma unroll
    for (int c = 0; c < 4; ++c)
        poB[c] = (uint32_t)(bpr * 64 + ((c ^ brx) << 4));
    const size_t bsrc = (g.brow + bpr) * Cc;

    // ldmatrix per-thread constants
    const int lr = l & 15, hsel = l >> 4;
    const int rowA = wm * 64 + lr, rowB = wn * 64 + lr;
    const int rxa = (rowA >> 1) & 3, rxb = (rowB >> 1) & 3;
    const uint32_t aswz[2] = { (uint32_t)((hsel ^ rxa) << 4),
                               (uint32_t)(((2 + hsel) ^ rxa) << 4) };
    const uint32_t bswz[2] = { (uint32_t)((hsel ^ rxb) << 4),
                               (uint32_t)(((2 + hsel) ^ rxb) << 4) };
    const uint32_t abase = (uint32_t)(rowA * 64);
    const uint32_t bbase = (uint32_t)(rowB * 64);

#pragma unroll
    for (int mt = 0; mt < 4; ++mt)
#pragma unroll
        for (int ni = 0; ni < 8; ++ni)
#pragma unroll
            for (int q = 0; q < 4; ++q) acc[mt][ni][q] = 0.f;

    const int NIT = Cc / 32;    // 24

#define FILL_STAGE(DB, KT) do {                                               \
        CP16((DB) + poA0,            g.Ahi + asrc + (KT));                    \
        CP16((DB) + poA1,            g.Ahi + asrc + (KT) + 8);                \
        CP16((DB) + A_LO_OFF + poA0, g.Alo + asrc + (KT));                    \
        CP16((DB) + A_LO_OFF + poA1, g.Alo + asrc + (KT) + 8);                \
        _Pragma("unroll")                                                     \
        for (int c = 0; c < 4; ++c) {                                         \
            CP16((DB) + B_HI_OFF + poB[c], g.Bhi + bsrc + (KT) + c * 8);      \
            CP16((DB) + B_LO_OFF + poB[c], g.Blo + bsrc + (KT) + c * 8);      \
        }                                                                     \
    } while (0)

    // prologue: fill stages 0,1
#pragma unroll
    for (int s = 0; s < 2; ++s) {
        FILL_STAGE(sb + s * STAGE_SZ, s * 32);
        CPCOMMIT();
    }

    int buf = 0, fbuf = 2;
    for (int it = 0; it < NIT; ++it) {
        CPWAIT1();            // stage `it` landed
        __syncthreads();      // all warps done reading the fbuf buffer

        if (it + 2 < NIT)
            FILL_STAGE(sb + fbuf * STAGE_SZ, (it + 2) * 32);
        CPCOMMIT();

        const uint32_t tb = sb + buf * STAGE_SZ;
#pragma unroll
        for (int kk = 0; kk < 2; ++kk) {
            uint32_t ah[4][4], al[4][4], bh[4][4], bl[4][4];
#pragma unroll
            for (int mt = 0; mt < 4; ++mt) {
                uint32_t o = abase + mt * 1024 + aswz[kk];
                LDSM4(ah[mt], tb + o);
                LDSM4(al[mt], tb + A_LO_OFF + o);
            }
#pragma unroll
            for (int nt = 0; nt < 4; ++nt) {
                uint32_t o = bbase + nt * 1024 + bswz[kk];
                LDSM4(bh[nt], tb + B_HI_OFF + o);
                LDSM4(bl[nt], tb + B_LO_OFF + o);
            }
#pragma unroll
            for (int mt = 0; mt < 4; ++mt)
#pragma unroll
                for (int nt = 0; nt < 4; ++nt)
#pragma unroll
                    for (int h = 0; h < 2; ++h) {
                        float* c = acc[mt][nt * 2 + h];
                        MMA16816(c, ah[mt], bh[nt][h], bh[nt][h + 2]);
                        MMA16816(c, ah[mt], bl[nt][h], bl[nt][h + 2]);
                        MMA16816(c, al[mt], bh[nt][h], bh[nt][h + 2]);
                    }
        }
        buf = (buf == 2) ? 0 : buf + 1;
        fbuf = (fbuf == 2) ? 0 : fbuf + 1;
    }
    CPWAIT0();
#undef FILL_STAGE
}

// ---------------------------------------------------------------------------
// Kernel 1: QKV GEMM.  Y = X @ Wqkv^T, scatter epilogue into [t][b][h][d][n].
// Grid (9 j-tiles of 256, 256 m-tiles of 128), 256 threads.
// ---------------------------------------------------------------------------
__global__ __launch_bounds__(256, 1) void qkv_mma_kernel() {
    extern __shared__ __align__(128) char sm[];
    const int tid = threadIdx.x, l = tid & 31, w = tid >> 5;
    const int wm = w & 1, wn = w >> 1;
    const int j0 = blockIdx.x * 256, m0 = blockIdx.y * 128;

    GemmCtx g;
    g.Ahi = g_x_hi;  g.Alo = g_x_lo;  g.arow = (size_t)m0;
    g.Bhi = g_wq_hi; g.Blo = g_wq_lo; g.brow = (size_t)j0;

    float acc[4][8][4];
    gemm_mainloop(sm, g, acc);

    // Epilogue: 4 chunks of 64 j-cols; stage[j][m], coalesced scatter
    float* stage = (float*)sm;     // 64 x 132 floats
    const int b = m0 >> 12, nb = m0 & (Nn - 1);
#pragma unroll
    for (int c = 0; c < 4; ++c) {
        __syncthreads();
        if (wn == c) {
#pragma unroll
            for (int mt = 0; mt < 4; ++mt)
#pragma unroll
                for (int ni = 0; ni < 8; ++ni) {
                    int nt = ni >> 1, h = ni & 1;
                    int jl = nt * 16 + h * 8 + (l & 3) * 2;
                    int ml = wm * 64 + mt * 16 + (l >> 2);
                    const float* d = acc[mt][ni];
                    stage[jl * 132 + ml] = d[0];
                    stage[(jl + 1) * 132 + ml] = d[1];
                    stage[jl * 132 + ml + 8] = d[2];
                    stage[(jl + 1) * 132 + ml + 8] = d[3];
                }
        }
        __syncthreads();
        {
            int jl = tid >> 2, f4 = tid & 3;
            int j = j0 + c * 64 + jl;
            int t = j / Cc, r = j - t * Cc;
            float* dst = g_qkv + ((size_t)(t * Bz + b) * Cc + r) * Nn + nb;
#pragma unroll
            for (int i = 0; i < 8; ++i) {
                int idx = f4 + i * 4;
                *(float4*)(dst + idx * 4) = *(float4*)(stage + jl * 132 + idx * 4);
            }
        }
    }
}

// ---------------------------------------------------------------------------
// Kernel 6: proj GEMM.  out = ctx @ Wp^T + bias, row-major epilogue.
// Grid (3 j-tiles of 256, 256 m-tiles of 128), 256 threads.
// ---------------------------------------------------------------------------
__global__ __launch_bounds__(256, 1) void proj_mma_kernel(
    const float* __restrict__ bias, float* __restrict__ out) {
    extern __shared__ __align__(128) char sm[];
    const int tid = threadIdx.x, l = tid & 31, w = tid >> 5;
    const int wm = w & 1, wn = w >> 1;
    const int j0 = blockIdx.x * 256, m0 = blockIdx.y * 128;

    GemmCtx g;
    g.Ahi = g_ctx_hi; g.Alo = g_ctx_lo; g.arow = (size_t)m0;
    g.Bhi = g_wp_hi;  g.Blo = g_wp_lo;  g.brow = (size_t)j0;

    float acc[4][8][4];
    gemm_mainloop(sm, g, acc);

    // Epilogue: 4 chunks of 64 j-cols; stage[m][j], coalesced store + bias
    float* stage = (float*)sm;     // 128 x 68 floats
#pragma unroll
    for (int c = 0; c < 4; ++c) {
        __syncthreads();
        if (wn == c) {
#pragma unroll
            for (int mt = 0; mt < 4; ++mt)
#pragma unroll
                for (int ni = 0; ni < 8; ++ni) {
                    int nt = ni >> 1, h = ni & 1;
                    int jl = nt * 16 + h * 8 + (l & 3) * 2;
                    int ml = wm * 64 + mt * 16 + (l >> 2);
                    const float* d = acc[mt][ni];
                    stage[ml * 68 + jl] = d[0];
                    stage[ml * 68 + jl + 1] = d[1];
                    stage[(ml + 8) * 68 + jl] = d[2];
                    stage[(ml + 8) * 68 + jl + 1] = d[3];
                }
        }
        __syncthreads();
        {
            int ml = tid >> 1, half = tid & 1;
            int jb = j0 + c * 64 + half * 32;
#pragma unroll
            for (int i = 0; i < 8; ++i) {
                float4 v = *(float4*)(stage + ml * 68 + half * 32 + i * 4);
                float4 bb = *(const float4*)(bias + jb + i * 4);
                v.x += bb.x; v.y += bb.y; v.z += bb.z; v.w += bb.w;
                *(float4*)(out + (size_t)(m0 + ml) * Cc + jb + i * 4) = v;
            }
        }
    }
}

// ---------------------------------------------------------------------------
// Kernel 2: inverse L2 norms over N for q and k rows
// ---------------------------------------------------------------------------
__global__ __launch_bounds__(256) void norms_kernel() {
    int idx = blockIdx.x;
    const float4* p4 = (const float4*)(g_qkv + (size_t)idx * Nn);
    int tid = threadIdx.x;
    float s = 0.f;
    for (int i = tid; i < Nn / 4; i += 256) {
        float4 v = p4[i];
        s = fmaf(v.x, v.x, s); s = fmaf(v.y, v.y, s);
        s = fmaf(v.z, v.z, s); s = fmaf(v.w, v.w, s);
    }
#pragma unroll
    for (int o = 16; o; o >>= 1) s += __shfl_xor_sync(0xffffffffu, s, o);
    __shared__ float red[8];
    if ((tid & 31) == 0) red[tid >> 5] = s;
    __syncthreads();
    if (tid == 0) {
        float t = 0.f;
#pragma unroll
        for (int w = 0; w < 8; ++w) t += red[w];
        g_inv[idx] = 1.0f / fmaxf(sqrtf(t), 1e-12f);
    }
}

// ---------------------------------------------------------------------------
// Kernel 3: split-K attention gram (fp32)
// ---------------------------------------------------------------------------
__global__ __launch_bounds__(256) void attn_part_kernel() {
    __shared__ float Qs[96][33];
    __shared__ float Ks[96][33];
    int bh = blockIdx.x;
    int ch = blockIdx.y;
    const int NPC = Nn / ACHUNK;
    const float* qp = g_qkv + (size_t)bh * HD * Nn + ch * NPC;
    const float* kp = g_qkv + (size_t)ROWS * Nn + (size_t)bh * HD * Nn + ch * NPC;
    int tid = threadIdx.x;
    int tx = tid & 15, ty = tid >> 4;

    float acc[6][6];
#pragma unroll
    for (int i = 0; i < 6; ++i)
#pragma unroll
        for (int j = 0; j < 6; ++j) acc[i][j] = 0.f;

    for (int n0 = 0; n0 < NPC; n0 += 32) {
        int nl = tid & 31;
        for (int r = tid >> 5; r < 96; r += 8) {
            Qs[r][nl] = qp[(size_t)r * Nn + n0 + nl];
            Ks[r][nl] = kp[(size_t)r * Nn + n0 + nl];
        }
        __syncthreads();
#pragma unroll
        for (int e = 0; e < 32; ++e) {
            float rq[6], rk[6];
#pragma unroll
            for (int i = 0; i < 6; ++i) rq[i] = Qs[i * 16 + tx][e];
#pragma unroll
            for (int j = 0; j < 6; ++j) rk[j] = Ks[j * 16 + ty][e];
#pragma unroll
            for (int i = 0; i < 6; ++i)
#pragma unroll
                for (int j = 0; j < 6; ++j)
                    acc[i][j] = fmaf(rq[i], rk[j], acc[i][j]);
        }
        __syncthreads();
    }
    float* op = g_attn_part + ((size_t)ch * BH + bh) * (HD * HD);
#pragma unroll
    for (int i = 0; i < 6; ++i)
#pragma unroll
        for (int j = 0; j < 6; ++j)
            op[(i * 16 + tx) * HD + j * 16 + ty] = acc[i][j];
}

// ---------------------------------------------------------------------------
// Kernel 4: reduce + scale + softmax
// ---------------------------------------------------------------------------
__global__ __launch_bounds__(128) void softmax_kernel(const float* __restrict__ temperature) {
    int row = blockIdx.x;
    int bh = row / HD;
    int h = bh & (Hh - 1);
    int tid = threadIdx.x;

    float v = -1e30f;
    if (tid < HD) {
        float s = 0.f;
#pragma unroll
        for (int c = 0; c < ACHUNK; ++c)
            s += g_attn_part[((size_t)c * ROWS + row) * HD + tid];
        s *= g_inv[row] * g_inv[ROWS + bh * HD + tid] * temperature[h];
        v = s;
    }
    __shared__ float red[4];
    float m = v;
#pragma unroll
    for (int o = 16; o; o >>= 1) m = fmaxf(m, __shfl_xor_sync(0xffffffffu, m, o));
    if ((tid & 31) == 0) red[tid >> 5] = m;
    __syncthreads();
    m = fmaxf(fmaxf(red[0], red[1]), fmaxf(red[2], red[3]));
    float e = (tid < HD) ? expf(v - m) : 0.f;
    __syncthreads();
    float s2 = e;
#pragma unroll
    for (int o = 16; o; o >>= 1) s2 += __shfl_xor_sync(0xffffffffu, s2, o);
    if ((tid & 31) == 0) red[tid >> 5] = s2;
    __syncthreads();
    float denom = red[0] + red[1] + red[2] + red[3];
    if (tid < HD) g_attn[(size_t)row * HD + tid] = e / denom;
}

// ---------------------------------------------------------------------------
// Kernel 5: ctx = attn @ v, emits bf16 hi/lo in [m][c] layout (proj A operand)
// ---------------------------------------------------------------------------
__global__ __launch_bounds__(256) void ctx_kernel() {
    __shared__ float At[HD * HD];      // transposed attn: At[e*96 + d]
    __shared__ float Vs[16 * 128];
    int bh = blockIdx.x, n0 = blockIdx.y * 128;
    int tid = threadIdx.x, w = tid >> 5, lane = tid & 31;
    const float* vp = g_qkv + 2ull * ROWS * Nn + (size_t)bh * HD * Nn;

    for (int i = tid; i < HD * HD; i += 256) {
        int d = i / HD, e = i % HD;
        At[e * HD + d] = g_attn[(size_t)bh * HD * HD + i];
    }

    float acc[3][16];
#pragma unroll
    for (int dg = 0; dg < 3; ++dg)
#pragma unroll
        for (int nn = 0; nn < 16; ++nn) acc[dg][nn] = 0.f;

    for (int ec = 0; ec < HD / 16; ++ec) {
        __syncthreads();
        for (int i = tid; i < 16 * 128; i += 256)
            Vs[i] = vp[(size_t)(ec * 16 + (i >> 7)) * Nn + n0 + (i & 127)];
        __syncthreads();
#pragma unroll
        for (int e = 0; e < 16; ++e) {
            float a0 = At[(ec * 16 + e) * HD + lane];
            float a1 = At[(ec * 16 + e) * HD + 32 + lane];
            float a2 = At[(ec * 16 + e) * HD + 64 + lane];
#pragma unroll
            for (int nn = 0; nn < 16; ++nn) {
                float vv = Vs[e * 128 + w * 16 + nn];
                acc[0][nn] = fmaf(a0, vv, acc[0][nn]);
                acc[1][nn] = fmaf(a1, vv, acc[1][nn]);
                acc[2][nn] = fmaf(a2, vv, acc[2][nn]);
            }
        }
    }
    int b = bh >> 3, h = bh & 7;
#pragma unroll
    for (int dg = 0; dg < 3; ++dg)
#pragma unroll
        for (int nn = 0; nn < 16; ++nn) {
            float v = acc[dg][nn];
            __nv_bfloat16 hi = __float2bfloat16(v);
            __nv_bfloat16 lo = __float2bfloat16(v - __bfloat162float(hi));
            size_t base = ((size_t)(b * Nn + n0 + w * 16 + nn)) * Cc + h * HD + dg * 32 + lane;
            g_ctx_hi[base] = hi;
            g_ctx_lo[base] = lo;
        }
}

// ---------------------------------------------------------------------------
// Launcher
// ---------------------------------------------------------------------------
extern "C" void kernel_launch(void* const* d_in, const int* in_sizes, int n_in,
                              void* d_out, int out_size) {
    const float* x      = (const float*)d_in[0];
    const float* w_qkv  = (const float*)d_in[1];
    const float* temp   = (const float*)d_in[2];
    const float* w_proj = (const float*)d_in[3];
    const float* b_proj = (const float*)d_in[4];
    float* out = (float*)d_out;

    __nv_bfloat16 *xh, *xl, *qh, *ql, *ph, *pl;
    cudaGetSymbolAddress((void**)&xh, g_x_hi);
    cudaGetSymbolAddress((void**)&xl, g_x_lo);
    cudaGetSymbolAddress((void**)&qh, g_wq_hi);
    cudaGetSymbolAddress((void**)&ql, g_wq_lo);
    cudaGetSymbolAddress((void**)&ph, g_wp_hi);
    cudaGetSymbolAddress((void**)&pl, g_wp_lo);

    cudaFuncSetAttribute(qkv_mma_kernel,
                         cudaFuncAttributeMaxDynamicSharedMemorySize, SMEM_GEMM);
    cudaFuncSetAttribute(proj_mma_kernel,
                         cudaFuncAttributeMaxDynamicSharedMemorySize, SMEM_GEMM);

    const int nx = M1 * Cc / 4, nq = 3 * Cc * Cc / 4, np = Cc * Cc / 4;
    split_kernel<<<(nx + 255) / 256, 256>>>(x, xh, xl, nx);
    split_kernel<<<(nq + 255) / 256, 256>>>(w_qkv, qh, ql, nq);
    split_kernel<<<(np + 255) / 256, 256>>>(w_proj, ph, pl, np);

    qkv_mma_kernel<<<dim3(3 * Cc / 256, M1 / 128), 256, SMEM_GEMM>>>();
    norms_kernel<<<2 * ROWS, 256>>>();
    attn_part_kernel<<<dim3(BH, ACHUNK), 256>>>();
    softmax_kernel<<<ROWS, 128>>>(temp);
    ctx_kernel<<<dim3(BH, Nn / 128), 256>>>();
    proj_mma_kernel<<<dim3(Cc / 256, M1 / 128), 256, SMEM_GEMM>>>(b_proj, out);
}

// round 7
// speedup vs baseline: 1.2457x; 1.2457x over previous
#include <cuda_runtime.h>
#include <cuda_bf16.h>
#include <math.h>
#include <cstdint>

// Problem constants
#define Bz   8
#define Nn   4096
#define Cc   768
#define Hh   8
#define HD   96
#define M1   (Bz * Nn)          // 32768 tokens
#define BH   (Bz * Hh)          // 64
#define ROWS (BH * HD)          // 6144 rows per tensor (q or k)
#define ACHUNK 8                // split-K chunks for attention gram

// ---------------------------------------------------------------------------
// Device scratch.  qkv stored as bf16 hi/lo pairs: row = t*ROWS + bh*96 + d
// ---------------------------------------------------------------------------
__device__ __nv_bfloat16 g_qkvh[3ull * ROWS * Nn];
__device__ __nv_bfloat16 g_qkvl[3ull * ROWS * Nn];
__device__ float g_inv[2 * ROWS];
__device__ float g_attn_part[(size_t)ACHUNK * BH * HD * HD];
__device__ float g_attn[(size_t)BH * HD * HD];
__device__ __nv_bfloat16 g_ctx_hi[(size_t)M1 * Cc];          // ctx [m][c] hi
__device__ __nv_bfloat16 g_ctx_lo[(size_t)M1 * Cc];          // ctx [m][c] lo
__device__ __nv_bfloat16 g_x_hi[(size_t)M1 * Cc];
__device__ __nv_bfloat16 g_x_lo[(size_t)M1 * Cc];
__device__ __nv_bfloat16 g_wq_hi[3 * Cc * Cc];
__device__ __nv_bfloat16 g_wq_lo[3 * Cc * Cc];
__device__ __nv_bfloat16 g_wp_hi[Cc * Cc];
__device__ __nv_bfloat16 g_wp_lo[Cc * Cc];

// ---------------------------------------------------------------------------
// PTX helpers (baseline target: mma.sync + ldmatrix + cp.async only)
// ---------------------------------------------------------------------------
#define LDSM4(R, A)                                                           \
    asm volatile("ldmatrix.sync.aligned.m8n8.x4.shared.b16 {%0,%1,%2,%3}, [%4];" \
        : "=r"((R)[0]), "=r"((R)[1]), "=r"((R)[2]), "=r"((R)[3]) : "r"(A))

#define MMA16816(C, A, B0, B1)                                                \
    asm volatile("mma.sync.aligned.m16n8k16.row.col.f32.bf16.bf16.f32 "       \
        "{%0,%1,%2,%3}, {%4,%5,%6,%7}, {%8,%9}, {%0,%1,%2,%3};"               \
        : "+f"((C)[0]), "+f"((C)[1]), "+f"((C)[2]), "+f"((C)[3])              \
        : "r"((A)[0]), "r"((A)[1]), "r"((A)[2]), "r"((A)[3]), "r"(B0), "r"(B1))

#define CP16(d, s)                                                            \
    asm volatile("cp.async.cg.shared.global [%0], [%1], 16;" :: "r"(d), "l"(s))
#define CPCOMMIT() asm volatile("cp.async.commit_group;" ::: "memory")
#define CPWAIT1()  asm volatile("cp.async.wait_group 1;" ::: "memory")
#define CPWAIT0()  asm volatile("cp.async.wait_group 0;" ::: "memory")

__device__ __forceinline__ void split2(float x, float y, uint32_t& hi, uint32_t& lo) {
    __nv_bfloat16 hx = __float2bfloat16(x), hy = __float2bfloat16(y);
    __nv_bfloat16 lx = __float2bfloat16(x - __bfloat162float(hx));
    __nv_bfloat16 ly = __float2bfloat16(y - __bfloat162float(hy));
    hi = (uint32_t)__bfloat16_as_ushort(hx) | ((uint32_t)__bfloat16_as_ushort(hy) << 16);
    lo = (uint32_t)__bfloat16_as_ushort(lx) | ((uint32_t)__bfloat16_as_ushort(ly) << 16);
}

// Main GEMM smem pipeline (round-5 config): tile = 128 rows x 64B swizzled = 8KB
// stage = 4 tiles = 32KB ; 3 stages = 96KB (dynamic)
#define TILE_SZ  8192
#define STAGE_SZ 32768
#define SMEM_GEMM (3 * STAGE_SZ)

// attn_part smem: tile = 96 rows x 48B (32B data + 16B pad) = 4608B
// stage = 4 tiles = 18432B ; 3 stages = 55296B (dynamic)
#define AT_TILE  4608
#define AT_STAGE 18432
#define SMEM_ATT (3 * AT_STAGE)

// ---------------------------------------------------------------------------
// Kernel 0: fp32 -> bf16 hi/lo split (prep)
// ---------------------------------------------------------------------------
__global__ __launch_bounds__(256) void split_kernel(
    const float* __restrict__ src, __nv_bfloat16* __restrict__ hi,
    __nv_bfloat16* __restrict__ lo, int n4) {
    int i = blockIdx.x * 256 + threadIdx.x;
    if (i < n4) {
        float4 v = ((const float4*)src)[i];
        uint2 h, l;
        split2(v.x, v.y, h.x, l.x);
        split2(v.z, v.w, h.y, l.y);
        ((uint2*)hi)[i] = h;
        ((uint2*)lo)[i] = l;
    }
}

// ---------------------------------------------------------------------------
// Main GEMM mainloop (round-5): 128x128 CTA tile, K-step 32, 3-stage cp.async,
// one __syncthreads per iteration. 8 warps (4M x 2N), 3-pass hi/lo bf16 MMA.
// Swizzle: smem offset(r, chunk) = r*64 + ((chunk ^ ((r>>1)&3)) << 4)
// ---------------------------------------------------------------------------
struct GemmCtx {
    const __nv_bfloat16 *Ahi, *Alo, *Bhi, *Blo;   // row-major [*, Cc]
    size_t arow, brow;
};

__device__ __forceinline__ void gemm_mainloop(
    char* sm, const GemmCtx& g, float acc[2][8][4]) {
    const int tid = threadIdx.x, l = tid & 31, w = tid >> 5;
    const int wm = w & 3, wn = w >> 2;
    const uint32_t sb = (uint32_t)__cvta_generic_to_shared(sm);

    const int pr = tid >> 1, pc0 = (tid & 1) * 2;
    const int prx = (pr >> 1) & 3;
    const uint32_t po0 = (uint32_t)(pr * 64 + ((pc0 ^ prx) << 4));
    const uint32_t po1 = (uint32_t)(pr * 64 + (((pc0 + 1) ^ prx) << 4));
    const size_t asrc = (g.arow + pr) * Cc + pc0 * 8;
    const size_t bsrc = (g.brow + pr) * Cc + pc0 * 8;

    const int lr = l & 15, hsel = l >> 4;
    const int rowA = wm * 32 + lr, rowB = wn * 64 + lr;
    const int rxa = (rowA >> 1) & 3, rxb = (rowB >> 1) & 3;
    const uint32_t aswz[2] = { (uint32_t)((hsel ^ rxa) << 4),
                               (uint32_t)(((2 + hsel) ^ rxa) << 4) };
    const uint32_t bswz[2] = { (uint32_t)((hsel ^ rxb) << 4),
                               (uint32_t)(((2 + hsel) ^ rxb) << 4) };
    const uint32_t abase = (uint32_t)(rowA * 64);
    const uint32_t bbase = (uint32_t)(rowB * 64);

#pragma unroll
    for (int mt = 0; mt < 2; ++mt)
#pragma unroll
        for (int ni = 0; ni < 8; ++ni)
#pragma unroll
            for (int q = 0; q < 4; ++q) acc[mt][ni][q] = 0.f;

    const int NIT = Cc / 32;    // 24

#define G_FILL(DB, KT) do {                                                   \
        CP16((DB) + po0,               g.Ahi + asrc + (KT));                  \
        CP16((DB) + po1,               g.Ahi + asrc + (KT) + 8);              \
        CP16((DB) + TILE_SZ + po0,     g.Alo + asrc + (KT));                  \
        CP16((DB) + TILE_SZ + po1,     g.Alo + asrc + (KT) + 8);              \
        CP16((DB) + 2 * TILE_SZ + po0, g.Bhi + bsrc + (KT));                  \
        CP16((DB) + 2 * TILE_SZ + po1, g.Bhi + bsrc + (KT) + 8);              \
        CP16((DB) + 3 * TILE_SZ + po0, g.Blo + bsrc + (KT));                  \
        CP16((DB) + 3 * TILE_SZ + po1, g.Blo + bsrc + (KT) + 8);              \
    } while (0)

#pragma unroll
    for (int s = 0; s < 2; ++s) {
        G_FILL(sb + s * STAGE_SZ, s * 32);
        CPCOMMIT();
    }

    int buf = 0, fbuf = 2;
    for (int it = 0; it < NIT; ++it) {
        CPWAIT1();
        __syncthreads();
        if (it + 2 < NIT)
            G_FILL(sb + fbuf * STAGE_SZ, (it + 2) * 32);
        CPCOMMIT();

        const uint32_t tb = sb + buf * STAGE_SZ;
#pragma unroll
        for (int kk = 0; kk < 2; ++kk) {
            uint32_t ah[2][4], al[2][4], bh[4][4], bl[4][4];
#pragma unroll
            for (int mt = 0; mt < 2; ++mt) {
                uint32_t o = abase + mt * 1024 + aswz[kk];
                LDSM4(ah[mt], tb + o);
                LDSM4(al[mt], tb + TILE_SZ + o);
            }
#pragma unroll
            for (int nt = 0; nt < 4; ++nt) {
                uint32_t o = bbase + nt * 1024 + bswz[kk];
                LDSM4(bh[nt], tb + 2 * TILE_SZ + o);
                LDSM4(bl[nt], tb + 3 * TILE_SZ + o);
            }
#pragma unroll
            for (int mt = 0; mt < 2; ++mt)
#pragma unroll
                for (int nt = 0; nt < 4; ++nt)
#pragma unroll
                    for (int h = 0; h < 2; ++h) {
                        float* c = acc[mt][nt * 2 + h];
                        MMA16816(c, ah[mt], bh[nt][h], bh[nt][h + 2]);
                        MMA16816(c, ah[mt], bl[nt][h], bl[nt][h + 2]);
                        MMA16816(c, al[mt], bh[nt][h], bh[nt][h + 2]);
                    }
        }
        buf = (buf == 2) ? 0 : buf + 1;
        fbuf = (fbuf == 2) ? 0 : fbuf + 1;
    }
    CPWAIT0();
#undef G_FILL
}

// ---------------------------------------------------------------------------
// Kernel 1: QKV GEMM.  Epilogue scatters bf16 hi/lo into [t][bh][d][n].
// Grid (18 j-tiles, 256 m-tiles), 256 threads.
// ---------------------------------------------------------------------------
__global__ __launch_bounds__(256) void qkv_mma_kernel() {
    extern __shared__ __align__(128) char sm[];
    const int tid = threadIdx.x, l = tid & 31, w = tid >> 5;
    const int wm = w & 3, wn = w >> 2;
    const int j0 = blockIdx.x * 128, m0 = blockIdx.y * 128;

    GemmCtx g;
    g.Ahi = g_x_hi;  g.Alo = g_x_lo;  g.arow = (size_t)m0;
    g.Bhi = g_wq_hi; g.Blo = g_wq_lo; g.brow = (size_t)j0;

    float acc[2][8][4];
    gemm_mainloop(sm, g, acc);

    float* stage = (float*)sm;     // 64 x 132 floats
    const int b = m0 >> 12, nb = m0 & (Nn - 1);
#pragma unroll
    for (int c = 0; c < 2; ++c) {
        __syncthreads();
        if (wn == c) {
#pragma unroll
            for (int mt = 0; mt < 2; ++mt)
#pragma unroll
                for (int ni = 0; ni < 8; ++ni) {
                    int nt = ni >> 1, h = ni & 1;
                    int jl = nt * 16 + h * 8 + (l & 3) * 2;
                    int ml = wm * 32 + mt * 16 + (l >> 2);
                    const float* d = acc[mt][ni];
                    stage[jl * 132 + ml] = d[0];
                    stage[(jl + 1) * 132 + ml] = d[1];
                    stage[jl * 132 + ml + 8] = d[2];
                    stage[(jl + 1) * 132 + ml + 8] = d[3];
                }
        }
        __syncthreads();
        {
            int jl = tid >> 2, f4 = tid & 3;
            int j = j0 + c * 64 + jl;
            int t = j / Cc, r = j - t * Cc;
            size_t base = ((size_t)t * ROWS + b * Cc + r) * Nn + nb;
#pragma unroll
            for (int i = 0; i < 8; ++i) {
                int idx = f4 + i * 4;
                float4 v = *(float4*)(stage + jl * 132 + idx * 4);
                uint2 h2, l2;
                split2(v.x, v.y, h2.x, l2.x);
                split2(v.z, v.w, h2.y, l2.y);
                *(uint2*)(g_qkvh + base + idx * 4) = h2;
                *(uint2*)(g_qkvl + base + idx * 4) = l2;
            }
        }
    }
}

// ---------------------------------------------------------------------------
// Kernel 6: proj GEMM.  out = ctx @ Wp^T + bias, row-major epilogue.
// ---------------------------------------------------------------------------
__global__ __launch_bounds__(256) void proj_mma_kernel(
    const float* __restrict__ bias, float* __restrict__ out) {
    extern __shared__ __align__(128) char sm[];
    const int tid = threadIdx.x, l = tid & 31, w = tid >> 5;
    const int wm = w & 3, wn = w >> 2;
    const int j0 = blockIdx.x * 128, m0 = blockIdx.y * 128;

    GemmCtx g;
    g.Ahi = g_ctx_hi; g.Alo = g_ctx_lo; g.arow = (size_t)m0;
    g.Bhi = g_wp_hi;  g.Blo = g_wp_lo;  g.brow = (size_t)j0;

    float acc[2][8][4];
    gemm_mainloop(sm, g, acc);

    float* stage = (float*)sm;     // 128 x 68 floats
#pragma unroll
    for (int c = 0; c < 2; ++c) {
        __syncthreads();
        if (wn == c) {
#pragma unroll
            for (int mt = 0; mt < 2; ++mt)
#pragma unroll
                for (int ni = 0; ni < 8; ++ni) {
                    int nt = ni >> 1, h = ni & 1;
                    int jl = nt * 16 + h * 8 + (l & 3) * 2;
                    int ml = wm * 32 + mt * 16 + (l >> 2);
                    const float* d = acc[mt][ni];
                    stage[ml * 68 + jl] = d[0];
                    stage[ml * 68 + jl + 1] = d[1];
                    stage[(ml + 8) * 68 + jl] = d[2];
                    stage[(ml + 8) * 68 + jl + 1] = d[3];
                }
        }
        __syncthreads();
        {
            int ml = tid >> 1, half = tid & 1;
            int jb = j0 + c * 64 + half * 32;
#pragma unroll
            for (int i = 0; i < 8; ++i) {
                float4 v = *(float4*)(stage + ml * 68 + half * 32 + i * 4);
                float4 bb = *(const float4*)(bias + jb + i * 4);
                v.x += bb.x; v.y += bb.y; v.z += bb.z; v.w += bb.w;
                *(float4*)(out + (size_t)(m0 + ml) * Cc + jb + i * 4) = v;
            }
        }
    }
}

// ---------------------------------------------------------------------------
// Kernel 2: inverse L2 norms over N (reads hi+lo).  idx in [0, 2*ROWS).
// ---------------------------------------------------------------------------
__global__ __launch_bounds__(256) void norms_kernel() {
    size_t row = blockIdx.x;
    const uint2* hp = (const uint2*)(g_qkvh + row * Nn);
    const uint2* lp = (const uint2*)(g_qkvl + row * Nn);
    int tid = threadIdx.x;
    float s = 0.f;
    for (int i = tid; i < Nn / 4; i += 256) {
        uint2 hu = hp[i], lu = lp[i];
        float2 h0 = __bfloat1622float2(*(__nv_bfloat162*)&hu.x);
        float2 h1 = __bfloat1622float2(*(__nv_bfloat162*)&hu.y);
        float2 l0 = __bfloat1622float2(*(__nv_bfloat162*)&lu.x);
        float2 l1 = __bfloat1622float2(*(__nv_bfloat162*)&lu.y);
        float a = h0.x + l0.x, b = h0.y + l0.y;
        float c = h1.x + l1.x, d = h1.y + l1.y;
        s = fmaf(a, a, s); s = fmaf(b, b, s);
        s = fmaf(c, c, s); s = fmaf(d, d, s);
    }
#pragma unroll
    for (int o = 16; o; o >>= 1) s += __shfl_xor_sync(0xffffffffu, s, o);
    __shared__ float red[8];
    if ((tid & 31) == 0) red[tid >> 5] = s;
    __syncthreads();
    if (tid == 0) {
        float t = 0.f;
#pragma unroll
        for (int w = 0; w < 8; ++w) t += red[w];
        g_inv[row] = 1.0f / fmaxf(sqrtf(t), 1e-12f);
    }
}

// ---------------------------------------------------------------------------
// Kernel 3: attention gram via HMMA (3-pass hi/lo bf16).
// part[ch][bh][d][e] = sum_{n in chunk} q[d][n] * k[e][n]
// Block (bh, ch): 192 threads = 6 warps, warp = one m16 band, N=96, KC=16.
// Tile rows padded to 48B -> bank-group = (3r + hsel) mod 8, conflict-free.
// ---------------------------------------------------------------------------
__global__ __launch_bounds__(192) void attn_part_kernel() {
    extern __shared__ __align__(128) char sm[];
    const int tid = threadIdx.x, l = tid & 31, wm = tid >> 5;   // wm 0..5
    const int bh = blockIdx.x, ch = blockIdx.y;
    const int n0 = ch * (Nn / ACHUNK);                          // chunk of 512
    const uint32_t sb = (uint32_t)__cvta_generic_to_shared(sm);

    // producer: row pr (0..95), chunk pc (0 or 1) per tile
    const int pr = tid % 96, pc = tid / 96;
    const uint32_t po = (uint32_t)(pr * 48 + pc * 16);
    const size_t qsrc = ((size_t)bh * HD + pr) * Nn + n0 + pc * 8;
    const size_t ksrc = ((size_t)ROWS + (size_t)bh * HD + pr) * Nn + n0 + pc * 8;

    // ldmatrix constants
    const int lr = l & 15, hsel = l >> 4;
    const uint32_t aoff = (uint32_t)((wm * 16 + lr) * 48 + hsel * 16);
    const uint32_t boff = (uint32_t)(lr * 48 + hsel * 16);

    float acc[12][4];
#pragma unroll
    for (int i = 0; i < 12; ++i)
#pragma unroll
        for (int q = 0; q < 4; ++q) acc[i][q] = 0.f;

    const int NIT = (Nn / ACHUNK) / 16;    // 32

#define A_FILL(DB, KT) do {                                                   \
        CP16((DB) + po,               g_qkvh + qsrc + (KT));                  \
        CP16((DB) + AT_TILE + po,     g_qkvl + qsrc + (KT));                  \
        CP16((DB) + 2 * AT_TILE + po, g_qkvh + ksrc + (KT));                  \
        CP16((DB) + 3 * AT_TILE + po, g_qkvl + ksrc + (KT));                  \
    } while (0)

#pragma unroll
    for (int s = 0; s < 2; ++s) {
        A_FILL(sb + s * AT_STAGE, s * 16);
        CPCOMMIT();
    }

    int buf = 0, fbuf = 2;
    for (int it = 0; it < NIT; ++it) {
        CPWAIT1();
        __syncthreads();
        if (it + 2 < NIT)
            A_FILL(sb + fbuf * AT_STAGE, (it + 2) * 16);
        CPCOMMIT();

        const uint32_t tb = sb + buf * AT_STAGE;
        uint32_t ah[4], al[4], bhf[6][4], blf[6][4];
        LDSM4(ah, tb + aoff);
        LDSM4(al, tb + AT_TILE + aoff);
#pragma unroll
        for (int nt = 0; nt < 6; ++nt) {
            uint32_t o = boff + nt * (16 * 48);
            LDSM4(bhf[nt], tb + 2 * AT_TILE + o);
            LDSM4(blf[nt], tb + 3 * AT_TILE + o);
        }
#pragma unroll
        for (int nt = 0; nt < 6; ++nt)
#pragma unroll
            for (int h = 0; h < 2; ++h) {
                float* c = acc[nt * 2 + h];
                MMA16816(c, ah, bhf[nt][h], bhf[nt][h + 2]);
                MMA16816(c, ah, blf[nt][h], blf[nt][h + 2]);
                MMA16816(c, al, bhf[nt][h], bhf[nt][h + 2]);
            }
        buf = (buf == 2) ? 0 : buf + 1;
        fbuf = (fbuf == 2) ? 0 : fbuf + 1;
    }
    CPWAIT0();
#undef A_FILL

    // epilogue: fp32 partials
    float* op = g_attn_part + ((size_t)ch * BH + bh) * (HD * HD);
    const int r0 = wm * 16 + (l >> 2), cb = (l & 3) * 2;
#pragma unroll
    for (int nt = 0; nt < 6; ++nt)
#pragma unroll
        for (int h = 0; h < 2; ++h) {
            int col = nt * 16 + h * 8 + cb;
            const float* c = acc[nt * 2 + h];
            *(float2*)(op + r0 * HD + col) = make_float2(c[0], c[1]);
            *(float2*)(op + (r0 + 8) * HD + col) = make_float2(c[2], c[3]);
        }
}

// ---------------------------------------------------------------------------
// Kernel 4: reduce + scale + softmax
// ---------------------------------------------------------------------------
__global__ __launch_bounds__(128) void softmax_kernel(const float* __restrict__ temperature) {
    int row = blockIdx.x;
    int bh = row / HD;
    int h = bh & (Hh - 1);
    int tid = threadIdx.x;

    float v = -1e30f;
    if (tid < HD) {
        float s = 0.f;
#pragma unroll
        for (int c = 0; c < ACHUNK; ++c)
            s += g_attn_part[((size_t)c * ROWS + row) * HD + tid];
        s *= g_inv[row] * g_inv[ROWS + bh * HD + tid] * temperature[h];
        v = s;
    }
    __shared__ float red[4];
    float m = v;
#pragma unroll
    for (int o = 16; o; o >>= 1) m = fmaxf(m, __shfl_xor_sync(0xffffffffu, m, o));
    if ((tid & 31) == 0) red[tid >> 5] = m;
    __syncthreads();
    m = fmaxf(fmaxf(red[0], red[1]), fmaxf(red[2], red[3]));
    float e = (tid < HD) ? expf(v - m) : 0.f;
    __syncthreads();
    float s2 = e;
#pragma unroll
    for (int o = 16; o; o >>= 1) s2 += __shfl_xor_sync(0xffffffffu, s2, o);
    if ((tid & 31) == 0) red[tid >> 5] = s2;
    __syncthreads();
    float denom = red[0] + red[1] + red[2] + red[3];
    if (tid < HD) g_attn[(size_t)row * HD + tid] = e / denom;
}

// ---------------------------------------------------------------------------
// Kernel 5: ctx = attn @ v (v reconstructed hi+lo), emits bf16 hi/lo [m][c]
// ---------------------------------------------------------------------------
__global__ __launch_bounds__(256) void ctx_kernel() {
    __shared__ float At[HD * HD];      // transposed attn: At[e*96 + d]
    __shared__ float Vs[16 * 128];
    int bh = blockIdx.x, n0 = blockIdx.y * 128;
    int tid = threadIdx.x, w = tid >> 5, lane = tid & 31;
    const __nv_bfloat16* vh = g_qkvh + (2ull * ROWS + (size_t)bh * HD) * Nn;
    const __nv_bfloat16* vl = g_qkvl + (2ull * ROWS + (size_t)bh * HD) * Nn;

    for (int i = tid; i < HD * HD; i += 256) {
        int d = i / HD, e = i % HD;
        At[e * HD + d] = g_attn[(size_t)bh * HD * HD + i];
    }

    float acc[3][16];
#pragma unroll
    for (int dg = 0; dg < 3; ++dg)
#pragma unroll
        for (int nn = 0; nn < 16; ++nn) acc[dg][nn] = 0.f;

    for (int ec = 0; ec < HD / 16; ++ec) {
        __syncthreads();
        for (int i = tid; i < 16 * 128; i += 256) {
            size_t off = (size_t)(ec * 16 + (i >> 7)) * Nn + n0 + (i & 127);
            Vs[i] = __bfloat162float(vh[off]) + __bfloat162float(vl[off]);
        }
        __syncthreads();
#pragma unroll
        for (int e = 0; e < 16; ++e) {
            float a0 = At[(ec * 16 + e) * HD + lane];
            float a1 = At[(ec * 16 + e) * HD + 32 + lane];
            float a2 = At[(ec * 16 + e) * HD + 64 + lane];
#pragma unroll
            for (int nn = 0; nn < 16; ++nn) {
                float vv = Vs[e * 128 + w * 16 + nn];
                acc[0][nn] = fmaf(a0, vv, acc[0][nn]);
                acc[1][nn] = fmaf(a1, vv, acc[1][nn]);
                acc[2][nn] = fmaf(a2, vv, acc[2][nn]);
            }
        }
    }
    int b = bh >> 3, h = bh & 7;
#pragma unroll
    for (int dg = 0; dg < 3; ++dg)
#pragma unroll
        for (int nn = 0; nn < 16; ++nn) {
            float v = acc[dg][nn];
            __nv_bfloat16 hi = __float2bfloat16(v);
            __nv_bfloat16 lo = __float2bfloat16(v - __bfloat162float(hi));
            size_t base = ((size_t)(b * Nn + n0 + w * 16 + nn)) * Cc + h * HD + dg * 32 + lane;
            g_ctx_hi[base] = hi;
            g_ctx_lo[base] = lo;
        }
}

// ---------------------------------------------------------------------------
// Launcher
// ---------------------------------------------------------------------------
extern "C" void kernel_launch(void* const* d_in, const int* in_sizes, int n_in,
                              void* d_out, int out_size) {
    const float* x      = (const float*)d_in[0];
    const float* w_qkv  = (const float*)d_in[1];
    const float* temp   = (const float*)d_in[2];
    const float* w_proj = (const float*)d_in[3];
    const float* b_proj = (const float*)d_in[4];
    float* out = (float*)d_out;

    __nv_bfloat16 *xh, *xl, *qh, *ql, *ph, *pl;
    cudaGetSymbolAddress((void**)&xh, g_x_hi);
    cudaGetSymbolAddress((void**)&xl, g_x_lo);
    cudaGetSymbolAddress((void**)&qh, g_wq_hi);
    cudaGetSymbolAddress((void**)&ql, g_wq_lo);
    cudaGetSymbolAddress((void**)&ph, g_wp_hi);
    cudaGetSymbolAddress((void**)&pl, g_wp_lo);

    cudaFuncSetAttribute(qkv_mma_kernel,
                         cudaFuncAttributeMaxDynamicSharedMemorySize, SMEM_GEMM);
    cudaFuncSetAttribute(proj_mma_kernel,
                         cudaFuncAttributeMaxDynamicSharedMemorySize, SMEM_GEMM);
    cudaFuncSetAttribute(attn_part_kernel,
                         cudaFuncAttributeMaxDynamicSharedMemorySize, SMEM_ATT);

    const int nx = M1 * Cc / 4, nq = 3 * Cc * Cc / 4, np = Cc * Cc / 4;
    split_kernel<<<(nx + 255) / 256, 256>>>(x, xh, xl, nx);
    split_kernel<<<(nq + 255) / 256, 256>>>(w_qkv, qh, ql, nq);
    split_kernel<<<(np + 255) / 256, 256>>>(w_proj, ph, pl, np);

    qkv_mma_kernel<<<dim3(3 * Cc / 128, M1 / 128), 256, SMEM_GEMM>>>();
    norms_kernel<<<2 * ROWS, 256>>>();
    attn_part_kernel<<<dim3(BH, ACHUNK), 192, SMEM_ATT>>>();
    softmax_kernel<<<ROWS, 128>>>(temp);
    ctx_kernel<<<dim3(BH, Nn / 128), 256>>>();
    proj_mma_kernel<<<dim3(Cc / 128, M1 / 128), 256, SMEM_GEMM>>>(b_proj, out);
}

// round 8
// speedup vs baseline: 1.3442x; 1.0791x over previous
#include <cuda_runtime.h>
#include <cuda_bf16.h>
#include <math.h>
#include <cstdint>

// Problem constants
#define Bz   8
#define Nn   4096
#define Cc   768
#define Hh   8
#define HD   96
#define M1   (Bz * Nn)          // 32768 tokens
#define BH   (Bz * Hh)          // 64
#define ROWS (BH * HD)          // 6144 rows per tensor (q or k)
#define ACHUNK 8                // split-K chunks for attention gram

// ---------------------------------------------------------------------------
// Device scratch.  qkv stored as bf16 hi/lo pairs: row = t*ROWS + bh*96 + d
// ---------------------------------------------------------------------------
__device__ __nv_bfloat16 g_qkvh[3ull * ROWS * Nn];
__device__ __nv_bfloat16 g_qkvl[3ull * ROWS * Nn];
__device__ float g_inv[2 * ROWS];
__device__ float g_attn_part[(size_t)ACHUNK * BH * HD * HD];
__device__ float g_attn[(size_t)BH * HD * HD];
__device__ __nv_bfloat16 g_ctx_hi[(size_t)M1 * Cc];          // ctx [m][c] hi
__device__ __nv_bfloat16 g_ctx_lo[(size_t)M1 * Cc];          // ctx [m][c] lo
__device__ __nv_bfloat16 g_x_hi[(size_t)M1 * Cc];
__device__ __nv_bfloat16 g_x_lo[(size_t)M1 * Cc];
__device__ __nv_bfloat16 g_wq_hi[3 * Cc * Cc];
__device__ __nv_bfloat16 g_wq_lo[3 * Cc * Cc];
__device__ __nv_bfloat16 g_wp_hi[Cc * Cc];
__device__ __nv_bfloat16 g_wp_lo[Cc * Cc];

// ---------------------------------------------------------------------------
// PTX helpers (baseline target: mma.sync + ldmatrix + cp.async only)
// ---------------------------------------------------------------------------
#define LDSM4(R, A)                                                           \
    asm volatile("ldmatrix.sync.aligned.m8n8.x4.shared.b16 {%0,%1,%2,%3}, [%4];" \
        : "=r"((R)[0]), "=r"((R)[1]), "=r"((R)[2]), "=r"((R)[3]) : "r"(A))

#define LDSM4T(R, A)                                                          \
    asm volatile("ldmatrix.sync.aligned.m8n8.x4.trans.shared.b16 {%0,%1,%2,%3}, [%4];" \
        : "=r"((R)[0]), "=r"((R)[1]), "=r"((R)[2]), "=r"((R)[3]) : "r"(A))

#define MMA16816(C, A, B0, B1)                                                \
    asm volatile("mma.sync.aligned.m16n8k16.row.col.f32.bf16.bf16.f32 "       \
        "{%0,%1,%2,%3}, {%4,%5,%6,%7}, {%8,%9}, {%0,%1,%2,%3};"               \
        : "+f"((C)[0]), "+f"((C)[1]), "+f"((C)[2]), "+f"((C)[3])              \
        : "r"((A)[0]), "r"((A)[1]), "r"((A)[2]), "r"((A)[3]), "r"(B0), "r"(B1))

#define CP16(d, s)                                                            \
    asm volatile("cp.async.cg.shared.global [%0], [%1], 16;" :: "r"(d), "l"(s))
#define CPCOMMIT() asm volatile("cp.async.commit_group;" ::: "memory")
#define CPWAIT1()  asm volatile("cp.async.wait_group 1;" ::: "memory")
#define CPWAIT0()  asm volatile("cp.async.wait_group 0;" ::: "memory")

__device__ __forceinline__ void split2(float x, float y, uint32_t& hi, uint32_t& lo) {
    __nv_bfloat16 hx = __float2bfloat16(x), hy = __float2bfloat16(y);
    __nv_bfloat16 lx = __float2bfloat16(x - __bfloat162float(hx));
    __nv_bfloat16 ly = __float2bfloat16(y - __bfloat162float(hy));
    hi = (uint32_t)__bfloat16_as_ushort(hx) | ((uint32_t)__bfloat16_as_ushort(hy) << 16);
    lo = (uint32_t)__bfloat16_as_ushort(lx) | ((uint32_t)__bfloat16_as_ushort(ly) << 16);
}

// Main GEMM smem pipeline: tile = 128 rows x 64B swizzled = 8KB
// stage = 4 tiles = 32KB ; 3 stages = 96KB (dynamic)
#define TILE_SZ  8192
#define STAGE_SZ 32768
#define SMEM_GEMM (3 * STAGE_SZ)

// attn_part smem: tile = 96 rows x 48B = 4608B; stage = 4 tiles; 3 stages
#define AT_TILE  4608
#define AT_STAGE 18432
#define SMEM_ATT (3 * AT_STAGE)

// ctx smem layout: attn hi/lo tiles (96 x 208B) + v hi/lo tiles (96 x 272B)
#define CA_HI 0
#define CA_LO 19968
#define CV_HI 39936
#define CV_LO 66048
#define SMEM_CTX 92160

// ---------------------------------------------------------------------------
// Kernel 0: fp32 -> bf16 hi/lo split (prep)
// ---------------------------------------------------------------------------
__global__ __launch_bounds__(256) void split_kernel(
    const float* __restrict__ src, __nv_bfloat16* __restrict__ hi,
    __nv_bfloat16* __restrict__ lo, int n4) {
    int i = blockIdx.x * 256 + threadIdx.x;
    if (i < n4) {
        float4 v = ((const float4*)src)[i];
        uint2 h, l;
        split2(v.x, v.y, h.x, l.x);
        split2(v.z, v.w, h.y, l.y);
        ((uint2*)hi)[i] = h;
        ((uint2*)lo)[i] = l;
    }
}

// ---------------------------------------------------------------------------
// Main GEMM mainloop: 128x128 CTA tile, K-step 32, 3-stage cp.async,
// one __syncthreads per iteration. 8 warps (4M x 2N), 3-pass hi/lo bf16 MMA
// issued pass-outermost (no same-accumulator RAW chains).
// ---------------------------------------------------------------------------
struct GemmCtx {
    const __nv_bfloat16 *Ahi, *Alo, *Bhi, *Blo;   // row-major [*, Cc]
    size_t arow, brow;
};

__device__ __forceinline__ void gemm_mainloop(
    char* sm, const GemmCtx& g, float acc[2][8][4]) {
    const int tid = threadIdx.x, l = tid & 31, w = tid >> 5;
    const int wm = w & 3, wn = w >> 2;
    const uint32_t sb = (uint32_t)__cvta_generic_to_shared(sm);

    const int pr = tid >> 1, pc0 = (tid & 1) * 2;
    const int prx = (pr >> 1) & 3;
    const uint32_t po0 = (uint32_t)(pr * 64 + ((pc0 ^ prx) << 4));
    const uint32_t po1 = (uint32_t)(pr * 64 + (((pc0 + 1) ^ prx) << 4));
    const size_t asrc = (g.arow + pr) * Cc + pc0 * 8;
    const size_t bsrc = (g.brow + pr) * Cc + pc0 * 8;

    const int lr = l & 15, hsel = l >> 4;
    const int rowA = wm * 32 + lr, rowB = wn * 64 + lr;
    const int rxa = (rowA >> 1) & 3, rxb = (rowB >> 1) & 3;
    const uint32_t aswz[2] = { (uint32_t)((hsel ^ rxa) << 4),
                               (uint32_t)(((2 + hsel) ^ rxa) << 4) };
    const uint32_t bswz[2] = { (uint32_t)((hsel ^ rxb) << 4),
                               (uint32_t)(((2 + hsel) ^ rxb) << 4) };
    const uint32_t abase = (uint32_t)(rowA * 64);
    const uint32_t bbase = (uint32_t)(rowB * 64);

#pragma unroll
    for (int mt = 0; mt < 2; ++mt)
#pragma unroll
        for (int ni = 0; ni < 8; ++ni)
#pragma unroll
            for (int q = 0; q < 4; ++q) acc[mt][ni][q] = 0.f;

    const int NIT = Cc / 32;    // 24

#define G_FILL(DB, KT) do {                                                   \
        CP16((DB) + po0,               g.Ahi + asrc + (KT));                  \
        CP16((DB) + po1,               g.Ahi + asrc + (KT) + 8);              \
        CP16((DB) + TILE_SZ + po0,     g.Alo + asrc + (KT));                  \
        CP16((DB) + TILE_SZ + po1,     g.Alo + asrc + (KT) + 8);              \
        CP16((DB) + 2 * TILE_SZ + po0, g.Bhi + bsrc + (KT));                  \
        CP16((DB) + 2 * TILE_SZ + po1, g.Bhi + bsrc + (KT) + 8);              \
        CP16((DB) + 3 * TILE_SZ + po0, g.Blo + bsrc + (KT));                  \
        CP16((DB) + 3 * TILE_SZ + po1, g.Blo + bsrc + (KT) + 8);              \
    } while (0)

#pragma unroll
    for (int s = 0; s < 2; ++s) {
        G_FILL(sb + s * STAGE_SZ, s * 32);
        CPCOMMIT();
    }

    int buf = 0, fbuf = 2;
    for (int it = 0; it < NIT; ++it) {
        CPWAIT1();
        __syncthreads();
        if (it + 2 < NIT)
            G_FILL(sb + fbuf * STAGE_SZ, (it + 2) * 32);
        CPCOMMIT();

        const uint32_t tb = sb + buf * STAGE_SZ;
#pragma unroll
        for (int kk = 0; kk < 2; ++kk) {
            uint32_t ah[2][4], al[2][4], bh[4][4], bl[4][4];
#pragma unroll
            for (int mt = 0; mt < 2; ++mt) {
                uint32_t o = abase + mt * 1024 + aswz[kk];
                LDSM4(ah[mt], tb + o);
                LDSM4(al[mt], tb + TILE_SZ + o);
            }
#pragma unroll
            for (int nt = 0; nt < 4; ++nt) {
                uint32_t o = bbase + nt * 1024 + bswz[kk];
                LDSM4(bh[nt], tb + 2 * TILE_SZ + o);
                LDSM4(bl[nt], tb + 3 * TILE_SZ + o);
            }
            // pass-outermost: consecutive MMAs hit different accumulators
#pragma unroll
            for (int p = 0; p < 3; ++p)
#pragma unroll
                for (int mt = 0; mt < 2; ++mt)
#pragma unroll
                    for (int nt = 0; nt < 4; ++nt)
#pragma unroll
                        for (int h = 0; h < 2; ++h) {
                            const uint32_t* A = (p == 2) ? al[mt] : ah[mt];
                            const uint32_t* B = (p == 1) ? bl[nt] : bh[nt];
                            MMA16816(acc[mt][nt * 2 + h], A, B[h], B[h + 2]);
                        }
        }
        buf = (buf == 2) ? 0 : buf + 1;
        fbuf = (fbuf == 2) ? 0 : fbuf + 1;
    }
    CPWAIT0();
#undef G_FILL
}

// ---------------------------------------------------------------------------
// Kernel 1: QKV GEMM.  Epilogue scatters bf16 hi/lo into [t][bh][d][n].
// ---------------------------------------------------------------------------
__global__ __launch_bounds__(256) void qkv_mma_kernel() {
    extern __shared__ __align__(128) char sm[];
    const int tid = threadIdx.x, l = tid & 31, w = tid >> 5;
    const int wm = w & 3, wn = w >> 2;
    const int j0 = blockIdx.x * 128, m0 = blockIdx.y * 128;

    GemmCtx g;
    g.Ahi = g_x_hi;  g.Alo = g_x_lo;  g.arow = (size_t)m0;
    g.Bhi = g_wq_hi; g.Blo = g_wq_lo; g.brow = (size_t)j0;

    float acc[2][8][4];
    gemm_mainloop(sm, g, acc);

    float* stage = (float*)sm;     // 64 x 132 floats
    const int b = m0 >> 12, nb = m0 & (Nn - 1);
#pragma unroll
    for (int c = 0; c < 2; ++c) {
        __syncthreads();
        if (wn == c) {
#pragma unroll
            for (int mt = 0; mt < 2; ++mt)
#pragma unroll
                for (int ni = 0; ni < 8; ++ni) {
                    int nt = ni >> 1, h = ni & 1;
                    int jl = nt * 16 + h * 8 + (l & 3) * 2;
                    int ml = wm * 32 + mt * 16 + (l >> 2);
                    const float* d = acc[mt][ni];
                    stage[jl * 132 + ml] = d[0];
                    stage[(jl + 1) * 132 + ml] = d[1];
                    stage[jl * 132 + ml + 8] = d[2];
                    stage[(jl + 1) * 132 + ml + 8] = d[3];
                }
        }
        __syncthreads();
        {
            int jl = tid >> 2, f4 = tid & 3;
            int j = j0 + c * 64 + jl;
            int t = j / Cc, r = j - t * Cc;
            size_t base = ((size_t)t * ROWS + b * Cc + r) * Nn + nb;
#pragma unroll
            for (int i = 0; i < 8; ++i) {
                int idx = f4 + i * 4;
                float4 v = *(float4*)(stage + jl * 132 + idx * 4);
                uint2 h2, l2;
                split2(v.x, v.y, h2.x, l2.x);
                split2(v.z, v.w, h2.y, l2.y);
                *(uint2*)(g_qkvh + base + idx * 4) = h2;
                *(uint2*)(g_qkvl + base + idx * 4) = l2;
            }
        }
    }
}

// ---------------------------------------------------------------------------
// Kernel 6: proj GEMM.  out = ctx @ Wp^T + bias, row-major epilogue.
// ---------------------------------------------------------------------------
__global__ __launch_bounds__(256) void proj_mma_kernel(
    const float* __restrict__ bias, float* __restrict__ out) {
    extern __shared__ __align__(128) char sm[];
    const int tid = threadIdx.x, l = tid & 31, w = tid >> 5;
    const int wm = w & 3, wn = w >> 2;
    const int j0 = blockIdx.x * 128, m0 = blockIdx.y * 128;

    GemmCtx g;
    g.Ahi = g_ctx_hi; g.Alo = g_ctx_lo; g.arow = (size_t)m0;
    g.Bhi = g_wp_hi;  g.Blo = g_wp_lo;  g.brow = (size_t)j0;

    float acc[2][8][4];
    gemm_mainloop(sm, g, acc);

    float* stage = (float*)sm;     // 128 x 68 floats
#pragma unroll
    for (int c = 0; c < 2; ++c) {
        __syncthreads();
        if (wn == c) {
#pragma unroll
            for (int mt = 0; mt < 2; ++mt)
#pragma unroll
                for (int ni = 0; ni < 8; ++ni) {
                    int nt = ni >> 1, h = ni & 1;
                    int jl = nt * 16 + h * 8 + (l & 3) * 2;
                    int ml = wm * 32 + mt * 16 + (l >> 2);
                    const float* d = acc[mt][ni];
                    stage[ml * 68 + jl] = d[0];
                    stage[ml * 68 + jl + 1] = d[1];
                    stage[(ml + 8) * 68 + jl] = d[2];
                    stage[(ml + 8) * 68 + jl + 1] = d[3];
                }
        }
        __syncthreads();
        {
            int ml = tid >> 1, half = tid & 1;
            int jb = j0 + c * 64 + half * 32;
#pragma unroll
            for (int i = 0; i < 8; ++i) {
                float4 v = *(float4*)(stage + ml * 68 + half * 32 + i * 4);
                float4 bb = *(const float4*)(bias + jb + i * 4);
                v.x += bb.x; v.y += bb.y; v.z += bb.z; v.w += bb.w;
                *(float4*)(out + (size_t)(m0 + ml) * Cc + jb + i * 4) = v;
            }
        }
    }
}

// ---------------------------------------------------------------------------
// Kernel 2: inverse L2 norms over N (reads hi+lo).
// ---------------------------------------------------------------------------
__global__ __launch_bounds__(256) void norms_kernel() {
    size_t row = blockIdx.x;
    const uint2* hp = (const uint2*)(g_qkvh + row * Nn);
    const uint2* lp = (const uint2*)(g_qkvl + row * Nn);
    int tid = threadIdx.x;
    float s = 0.f;
    for (int i = tid; i < Nn / 4; i += 256) {
        uint2 hu = hp[i], lu = lp[i];
        float2 h0 = __bfloat1622float2(*(__nv_bfloat162*)&hu.x);
        float2 h1 = __bfloat1622float2(*(__nv_bfloat162*)&hu.y);
        float2 l0 = __bfloat1622float2(*(__nv_bfloat162*)&lu.x);
        float2 l1 = __bfloat1622float2(*(__nv_bfloat162*)&lu.y);
        float a = h0.x + l0.x, b = h0.y + l0.y;
        float c = h1.x + l1.x, d = h1.y + l1.y;
        s = fmaf(a, a, s); s = fmaf(b, b, s);
        s = fmaf(c, c, s); s = fmaf(d, d, s);
    }
#pragma unroll
    for (int o = 16; o; o >>= 1) s += __shfl_xor_sync(0xffffffffu, s, o);
    __shared__ float red[8];
    if ((tid & 31) == 0) red[tid >> 5] = s;
    __syncthreads();
    if (tid == 0) {
        float t = 0.f;
#pragma unroll
        for (int w = 0; w < 8; ++w) t += red[w];
        g_inv[row] = 1.0f / fmaxf(sqrtf(t), 1e-12f);
    }
}

// ---------------------------------------------------------------------------
// Kernel 3: attention gram via HMMA (3-pass, pass-outermost issue order).
// ---------------------------------------------------------------------------
__global__ __launch_bounds__(192) void attn_part_kernel() {
    extern __shared__ __align__(128) char sm[];
    const int tid = threadIdx.x, l = tid & 31, wm = tid >> 5;   // wm 0..5
    const int bh = blockIdx.x, ch = blockIdx.y;
    const int n0 = ch * (Nn / ACHUNK);                          // chunk of 512
    const uint32_t sb = (uint32_t)__cvta_generic_to_shared(sm);

    const int pr = tid % 96, pc = tid / 96;
    const uint32_t po = (uint32_t)(pr * 48 + pc * 16);
    const size_t qsrc = ((size_t)bh * HD + pr) * Nn + n0 + pc * 8;
    const size_t ksrc = ((size_t)ROWS + (size_t)bh * HD + pr) * Nn + n0 + pc * 8;

    const int lr = l & 15, hsel = l >> 4;
    const uint32_t aoff = (uint32_t)((wm * 16 + lr) * 48 + hsel * 16);
    const uint32_t boff = (uint32_t)(lr * 48 + hsel * 16);

    float acc[12][4];
#pragma unroll
    for (int i = 0; i < 12; ++i)
#pragma unroll
        for (int q = 0; q < 4; ++q) acc[i][q] = 0.f;

    const int NIT = (Nn / ACHUNK) / 16;    // 32

#define A_FILL(DB, KT) do {                                                   \
        CP16((DB) + po,               g_qkvh + qsrc + (KT));                  \
        CP16((DB) + AT_TILE + po,     g_qkvl + qsrc + (KT));                  \
        CP16((DB) + 2 * AT_TILE + po, g_qkvh + ksrc + (KT));                  \
        CP16((DB) + 3 * AT_TILE + po, g_qkvl + ksrc + (KT));                  \
    } while (0)

#pragma unroll
    for (int s = 0; s < 2; ++s) {
        A_FILL(sb + s * AT_STAGE, s * 16);
        CPCOMMIT();
    }

    int buf = 0, fbuf = 2;
    for (int it = 0; it < NIT; ++it) {
        CPWAIT1();
        __syncthreads();
        if (it + 2 < NIT)
            A_FILL(sb + fbuf * AT_STAGE, (it + 2) * 16);
        CPCOMMIT();

        const uint32_t tb = sb + buf * AT_STAGE;
        uint32_t ah[4], al[4], bhf[6][4], blf[6][4];
        LDSM4(ah, tb + aoff);
        LDSM4(al, tb + AT_TILE + aoff);
#pragma unroll
        for (int nt = 0; nt < 6; ++nt) {
            uint32_t o = boff + nt * (16 * 48);
            LDSM4(bhf[nt], tb + 2 * AT_TILE + o);
            LDSM4(blf[nt], tb + 3 * AT_TILE + o);
        }
#pragma unroll
        for (int p = 0; p < 3; ++p)
#pragma unroll
            for (int nt = 0; nt < 6; ++nt)
#pragma unroll
                for (int h = 0; h < 2; ++h) {
                    const uint32_t* A = (p == 2) ? al : ah;
                    const uint32_t* B = (p == 1) ? blf[nt] : bhf[nt];
                    MMA16816(acc[nt * 2 + h], A, B[h], B[h + 2]);
                }
        buf = (buf == 2) ? 0 : buf + 1;
        fbuf = (fbuf == 2) ? 0 : fbuf + 1;
    }
    CPWAIT0();
#undef A_FILL

    float* op = g_attn_part + ((size_t)ch * BH + bh) * (HD * HD);
    const int r0 = wm * 16 + (l >> 2), cb = (l & 3) * 2;
#pragma unroll
    for (int nt = 0; nt < 6; ++nt)
#pragma unroll
        for (int h = 0; h < 2; ++h) {
            int col = nt * 16 + h * 8 + cb;
            const float* c = acc[nt * 2 + h];
            *(float2*)(op + r0 * HD + col) = make_float2(c[0], c[1]);
            *(float2*)(op + (r0 + 8) * HD + col) = make_float2(c[2], c[3]);
        }
}

// ---------------------------------------------------------------------------
// Kernel 4: reduce + scale + softmax
// ---------------------------------------------------------------------------
__global__ __launch_bounds__(128) void softmax_kernel(const float* __restrict__ temperature) {
    int row = blockIdx.x;
    int bh = row / HD;
    int h = bh & (Hh - 1);
    int tid = threadIdx.x;

    float v = -1e30f;
    if (tid < HD) {
        float s = 0.f;
#pragma unroll
        for (int c = 0; c < ACHUNK; ++c)
            s += g_attn_part[((size_t)c * ROWS + row) * HD + tid];
        s *= g_inv[row] * g_inv[ROWS + bh * HD + tid] * temperature[h];
        v = s;
    }
    __shared__ float red[4];
    float m = v;
#pragma unroll
    for (int o = 16; o; o >>= 1) m = fmaxf(m, __shfl_xor_sync(0xffffffffu, m, o));
    if ((tid & 31) == 0) red[tid >> 5] = m;
    __syncthreads();
    m = fmaxf(fmaxf(red[0], red[1]), fmaxf(red[2], red[3]));
    float e = (tid < HD) ? expf(v - m) : 0.f;
    __syncthreads();
    float s2 = e;
#pragma unroll
    for (int o = 16; o; o >>= 1) s2 += __shfl_xor_sync(0xffffffffu, s2, o);
    if ((tid & 31) == 0) red[tid >> 5] = s2;
    __syncthreads();
    float denom = red[0] + red[1] + red[2] + red[3];
    if (tid < HD) g_attn[(size_t)row * HD + tid] = e / denom;
}

// ---------------------------------------------------------------------------
// Kernel 5: ctx = attn @ v via HMMA (3-pass hi/lo).
// Block (bh, n-tile of 128): M=96 (d), N=128 (n), K=96 (e). 6 warps.
// attn [d][e] hi/lo in smem (208B-pad rows, non-trans ldmatrix for A);
// v [e][n] hi/lo in smem (272B-pad rows, ldmatrix.trans for B fragments).
// ---------------------------------------------------------------------------
__global__ __launch_bounds__(192) void ctx_kernel() {
    extern __shared__ __align__(128) char sm[];
    const int tid = threadIdx.x, l = tid & 31, wm = tid >> 5;   // wm 0..5
    const int bh = blockIdx.x, n0 = blockIdx.y * 128;
    const uint32_t sb = (uint32_t)__cvta_generic_to_shared(sm);

    // v tile fill (once): 96 rows x 8 uint16x8 chunks, hi + lo
    const size_t vbase = (2ull * ROWS + (size_t)bh * HD) * Nn + n0;
#pragma unroll
    for (int k = 0; k < 8; ++k) {
        int c = tid + k * 192;
        int r = c >> 4, chk = c & 15;
        uint32_t dst = sb + CV_HI + r * 272 + chk * 16;
        CP16(dst, g_qkvh + vbase + (size_t)r * Nn + chk * 8);
        CP16(dst + (CV_LO - CV_HI), g_qkvl + vbase + (size_t)r * Nn + chk * 8);
    }
    CPCOMMIT();

    // attn tile fill + split (once): rows d, 104 bf16 per padded row
    {
        const float* ap = g_attn + (size_t)bh * HD * HD;
        __nv_bfloat16* Ahp = (__nv_bfloat16*)(sm + CA_HI);
        __nv_bfloat16* Alp = (__nv_bfloat16*)(sm + CA_LO);
        for (int i = tid; i < HD * HD; i += 192) {
            int d = i / HD, e = i - d * HD;
            float v = ap[i];
            __nv_bfloat16 hi = __float2bfloat16(v);
            __nv_bfloat16 lo = __float2bfloat16(v - __bfloat162float(hi));
            Ahp[d * 104 + e] = hi;
            Alp[d * 104 + e] = lo;
        }
    }
    CPWAIT0();
    __syncthreads();

    float acc[16][4];
#pragma unroll
    for (int i = 0; i < 16; ++i)
#pragma unroll
        for (int q = 0; q < 4; ++q) acc[i][q] = 0.f;

    const int lr = l & 15, hsel = l >> 4;
    const uint32_t aoff = sb + CA_HI + (uint32_t)((wm * 16 + lr) * 208 + hsel * 16);
    // trans-B lane address: e-row = (l&7) + 8*(l>>4), 16B chunk = (l>>3)&1
    const int be = (l & 7) + ((l >> 4) << 3);
    const uint32_t boff = sb + CV_HI + (uint32_t)(be * 272 + ((l >> 3) & 1) * 16);

#pragma unroll
    for (int kc = 0; kc < 6; ++kc) {
        uint32_t ah[4], al[4];
        LDSM4(ah, aoff + kc * 32);
        LDSM4(al, aoff + (CA_LO - CA_HI) + kc * 32);
#pragma unroll
        for (int nq = 0; nq < 8; ++nq) {
            uint32_t bhf[4], blf[4];
            uint32_t o = boff + (uint32_t)(kc * 16 * 272 + nq * 32);
            LDSM4T(bhf, o);
            LDSM4T(blf, o + (CV_LO - CV_HI));
#pragma unroll
            for (int p = 0; p < 3; ++p)
#pragma unroll
                for (int h = 0; h < 2; ++h) {
                    const uint32_t* A = (p == 2) ? al : ah;
                    const uint32_t* B = (p == 1) ? blf : bhf;
                    MMA16816(acc[nq * 2 + h], A, B[h], B[h + 2]);
                }
        }
    }

    // Epilogue: stage fp32 [n][d] (pad 100), then coalesced bf16 hi/lo out
    __syncthreads();
    float* stage = (float*)sm;
    {
        const int d0 = wm * 16 + (l >> 2), cb = (l & 3) * 2;
#pragma unroll
        for (int nq = 0; nq < 8; ++nq)
#pragma unroll
            for (int h = 0; h < 2; ++h) {
                int n = nq * 16 + h * 8 + cb;
                const float* c = acc[nq * 2 + h];
                stage[n * 100 + d0] = c[0];
                stage[(n + 1) * 100 + d0] = c[1];
                stage[n * 100 + d0 + 8] = c[2];
                stage[(n + 1) * 100 + d0 + 8] = c[3];
            }
    }
    __syncthreads();
    {
        const int b = bh >> 3, hh = bh & 7;
#pragma unroll
        for (int k = 0; k < 32; ++k) {
            int flat = tid + k * 192;
            int n = flat / 48, j = flat - n * 48;
            float v0 = stage[n * 100 + j * 2];
            float v1 = stage[n * 100 + j * 2 + 1];
            uint32_t hi, lo;
            split2(v0, v1, hi, lo);
            size_t addr = ((size_t)(b * Nn + n0 + n)) * Cc + hh * HD + j * 2;
            *(uint32_t*)(g_ctx_hi + addr) = hi;
            *(uint32_t*)(g_ctx_lo + addr) = lo;
        }
    }
}

// ---------------------------------------------------------------------------
// Launcher
// ---------------------------------------------------------------------------
extern "C" void kernel_launch(void* const* d_in, const int* in_sizes, int n_in,
                              void* d_out, int out_size) {
    const float* x      = (const float*)d_in[0];
    const float* w_qkv  = (const float*)d_in[1];
    const float* temp   = (const float*)d_in[2];
    const float* w_proj = (const float*)d_in[3];
    const float* b_proj = (const float*)d_in[4];
    float* out = (float*)d_out;

    __nv_bfloat16 *xh, *xl, *qh, *ql, *ph, *pl;
    cudaGetSymbolAddress((void**)&xh, g_x_hi);
    cudaGetSymbolAddress((void**)&xl, g_x_lo);
    cudaGetSymbolAddress((void**)&qh, g_wq_hi);
    cudaGetSymbolAddress((void**)&ql, g_wq_lo);
    cudaGetSymbolAddress((void**)&ph, g_wp_hi);
    cudaGetSymbolAddress((void**)&pl, g_wp_lo);

    cudaFuncSetAttribute(qkv_mma_kernel,
                         cudaFuncAttributeMaxDynamicSharedMemorySize, SMEM_GEMM);
    cudaFuncSetAttribute(proj_mma_kernel,
                         cudaFuncAttributeMaxDynamicSharedMemorySize, SMEM_GEMM);
    cudaFuncSetAttribute(attn_part_kernel,
                         cudaFuncAttributeMaxDynamicSharedMemorySize, SMEM_ATT);
    cudaFuncSetAttribute(ctx_kernel,
                         cudaFuncAttributeMaxDynamicSharedMemorySize, SMEM_CTX);

    const int nx = M1 * Cc / 4, nq = 3 * Cc * Cc / 4, np = Cc * Cc / 4;
    split_kernel<<<(nx + 255) / 256, 256>>>(x, xh, xl, nx);
    split_kernel<<<(nq + 255) / 256, 256>>>(w_qkv, qh, ql, nq);
    split_kernel<<<(np + 255) / 256, 256>>>(w_proj, ph, pl, np);

    qkv_mma_kernel<<<dim3(3 * Cc / 128, M1 / 128), 256, SMEM_GEMM>>>();
    norms_kernel<<<2 * ROWS, 256>>>();
    attn_part_kernel<<<dim3(BH, ACHUNK), 192, SMEM_ATT>>>();
    softmax_kernel<<<ROWS, 128>>>(temp);
    ctx_kernel<<<dim3(BH, Nn / 128), 192, SMEM_CTX>>>();
    proj_mma_kernel<<<dim3(Cc / 128, M1 / 128), 256, SMEM_GEMM>>>(b_proj, out);
}

// round 9
// speedup vs baseline: 1.3715x; 1.0203x over previous
#include <cuda_runtime.h>
#include <cuda_bf16.h>
#include <math.h>
#include <cstdint>

// Problem constants
#define Bz   8
#define Nn   4096
#define Cc   768
#define Hh   8
#define HD   96
#define M1   (Bz * Nn)          // 32768 tokens
#define BH   (Bz * Hh)          // 64
#define ROWS (BH * HD)          // 6144 rows per tensor (q or k)
#define ACHUNK 8                // split-K chunks for attention gram

// ---------------------------------------------------------------------------
// Device scratch.  qkv stored as bf16 hi/lo pairs: row = t*ROWS + bh*96 + d
// ---------------------------------------------------------------------------
__device__ __nv_bfloat16 g_qkvh[3ull * ROWS * Nn];
__device__ __nv_bfloat16 g_qkvl[3ull * ROWS * Nn];
__device__ float g_nsq[2 * ROWS * 32];               // per (row, m-tile) sumsq
__device__ float g_inv[2 * ROWS];
__device__ float g_attn_part[(size_t)ACHUNK * BH * HD * HD];
__device__ float g_attn[(size_t)BH * HD * HD];
__device__ __nv_bfloat16 g_ctx_hi[(size_t)M1 * Cc];          // ctx [m][c] hi
__device__ __nv_bfloat16 g_ctx_lo[(size_t)M1 * Cc];          // ctx [m][c] lo
__device__ __nv_bfloat16 g_x_hi[(size_t)M1 * Cc];
__device__ __nv_bfloat16 g_x_lo[(size_t)M1 * Cc];
__device__ __nv_bfloat16 g_wq_hi[3 * Cc * Cc];
__device__ __nv_bfloat16 g_wq_lo[3 * Cc * Cc];
__device__ __nv_bfloat16 g_wp_hi[Cc * Cc];
__device__ __nv_bfloat16 g_wp_lo[Cc * Cc];

// ---------------------------------------------------------------------------
// PTX helpers (baseline target: mma.sync + ldmatrix + cp.async only)
// ---------------------------------------------------------------------------
#define LDSM4(R, A)                                                           \
    asm volatile("ldmatrix.sync.aligned.m8n8.x4.shared.b16 {%0,%1,%2,%3}, [%4];" \
        : "=r"((R)[0]), "=r"((R)[1]), "=r"((R)[2]), "=r"((R)[3]) : "r"(A))

#define LDSM4T(R, A)                                                          \
    asm volatile("ldmatrix.sync.aligned.m8n8.x4.trans.shared.b16 {%0,%1,%2,%3}, [%4];" \
        : "=r"((R)[0]), "=r"((R)[1]), "=r"((R)[2]), "=r"((R)[3]) : "r"(A))

#define MMA16816(C, A, B0, B1)                                                \
    asm volatile("mma.sync.aligned.m16n8k16.row.col.f32.bf16.bf16.f32 "       \
        "{%0,%1,%2,%3}, {%4,%5,%6,%7}, {%8,%9}, {%0,%1,%2,%3};"               \
        : "+f"((C)[0]), "+f"((C)[1]), "+f"((C)[2]), "+f"((C)[3])              \
        : "r"((A)[0]), "r"((A)[1]), "r"((A)[2]), "r"((A)[3]), "r"(B0), "r"(B1))

#define CP16(d, s)                                                            \
    asm volatile("cp.async.cg.shared.global [%0], [%1], 16;" :: "r"(d), "l"(s))
#define CPCOMMIT() asm volatile("cp.async.commit_group;" ::: "memory")
#define CPWAIT2()  asm volatile("cp.async.wait_group 2;" ::: "memory")
#define CPWAIT0()  asm volatile("cp.async.wait_group 0;" ::: "memory")

__device__ __forceinline__ void split2(float x, float y, uint32_t& hi, uint32_t& lo) {
    __nv_bfloat16 hx = __float2bfloat16(x), hy = __float2bfloat16(y);
    __nv_bfloat16 lx = __float2bfloat16(x - __bfloat162float(hx));
    __nv_bfloat16 ly = __float2bfloat16(y - __bfloat162float(hy));
    hi = (uint32_t)__bfloat16_as_ushort(hx) | ((uint32_t)__bfloat16_as_ushort(hy) << 16);
    lo = (uint32_t)__bfloat16_as_ushort(lx) | ((uint32_t)__bfloat16_as_ushort(ly) << 16);
}

// Main GEMM smem pipeline: tile = 128 rows x 64B swizzled = 8KB
// stage = 4 tiles = 32KB ; 3 stages = 96KB (dynamic)
#define TILE_SZ  8192
#define STAGE_SZ 32768
#define SMEM_GEMM (3 * STAGE_SZ)

// attn_part smem: tile = 96 rows x 48B = 4608B; stage = 4 tiles; 3 stages
#define AT_TILE  4608
#define AT_STAGE 18432
#define SMEM_ATT (3 * AT_STAGE)

// ctx smem layout: attn hi/lo tiles (96 x 208B) + v hi/lo tiles (96 x 272B)
#define CA_HI 0
#define CA_LO 19968
#define CV_HI 39936
#define CV_LO 66048
#define SMEM_CTX 92160

// ---------------------------------------------------------------------------
// Kernel 0: fp32 -> bf16 hi/lo split (prep)
// ---------------------------------------------------------------------------
__global__ __launch_bounds__(256) void split_kernel(
    const float* __restrict__ src, __nv_bfloat16* __restrict__ hi,
    __nv_bfloat16* __restrict__ lo, int n4) {
    int i = blockIdx.x * 256 + threadIdx.x;
    if (i < n4) {
        float4 v = ((const float4*)src)[i];
        uint2 h, l;
        split2(v.x, v.y, h.x, l.x);
        split2(v.z, v.w, h.y, l.y);
        ((uint2*)hi)[i] = h;
        ((uint2*)lo)[i] = l;
    }
}

// ---------------------------------------------------------------------------
// Main GEMM mainloop: 128x128 CTA tile, K-step 32, 3-stage cp.async.
// Relaxed pipeline: sync -> fill -> commit -> wait_group 2 -> consume.
// 8 warps (4M x 2N), 3-pass hi/lo bf16 MMA (pass-outermost).
// ---------------------------------------------------------------------------
struct GemmCtx {
    const __nv_bfloat16 *Ahi, *Alo, *Bhi, *Blo;   // row-major [*, Cc]
    size_t arow, brow;
};

__device__ __forceinline__ void gemm_mainloop(
    char* sm, const GemmCtx& g, float acc[2][8][4]) {
    const int tid = threadIdx.x, l = tid & 31, w = tid >> 5;
    const int wm = w & 3, wn = w >> 2;
    const uint32_t sb = (uint32_t)__cvta_generic_to_shared(sm);

    const int pr = tid >> 1, pc0 = (tid & 1) * 2;
    const int prx = (pr >> 1) & 3;
    const uint32_t po0 = (uint32_t)(pr * 64 + ((pc0 ^ prx) << 4));
    const uint32_t po1 = (uint32_t)(pr * 64 + (((pc0 + 1) ^ prx) << 4));
    const size_t asrc = (g.arow + pr) * Cc + pc0 * 8;
    const size_t bsrc = (g.brow + pr) * Cc + pc0 * 8;

    const int lr = l & 15, hsel = l >> 4;
    const int rowA = wm * 32 + lr, rowB = wn * 64 + lr;
    const int rxa = (rowA >> 1) & 3, rxb = (rowB >> 1) & 3;
    const uint32_t aswz[2] = { (uint32_t)((hsel ^ rxa) << 4),
                               (uint32_t)(((2 + hsel) ^ rxa) << 4) };
    const uint32_t bswz[2] = { (uint32_t)((hsel ^ rxb) << 4),
                               (uint32_t)(((2 + hsel) ^ rxb) << 4) };
    const uint32_t abase = (uint32_t)(rowA * 64);
    const uint32_t bbase = (uint32_t)(rowB * 64);

#pragma unroll
    for (int mt = 0; mt < 2; ++mt)
#pragma unroll
        for (int ni = 0; ni < 8; ++ni)
#pragma unroll
            for (int q = 0; q < 4; ++q) acc[mt][ni][q] = 0.f;

    const int NIT = Cc / 32;    // 24

#define G_FILL(DB, KT) do {                                                   \
        CP16((DB) + po0,               g.Ahi + asrc + (KT));                  \
        CP16((DB) + po1,               g.Ahi + asrc + (KT) + 8);              \
        CP16((DB) + TILE_SZ + po0,     g.Alo + asrc + (KT));                  \
        CP16((DB) + TILE_SZ + po1,     g.Alo + asrc + (KT) + 8);              \
        CP16((DB) + 2 * TILE_SZ + po0, g.Bhi + bsrc + (KT));                  \
        CP16((DB) + 2 * TILE_SZ + po1, g.Bhi + bsrc + (KT) + 8);              \
        CP16((DB) + 3 * TILE_SZ + po0, g.Blo + bsrc + (KT));                  \
        CP16((DB) + 3 * TILE_SZ + po1, g.Blo + bsrc + (KT) + 8);              \
    } while (0)

#pragma unroll
    for (int s = 0; s < 2; ++s) {
        G_FILL(sb + s * STAGE_SZ, s * 32);
        CPCOMMIT();
    }

    int buf = 0, fbuf = 2;
    for (int it = 0; it < NIT; ++it) {
        __syncthreads();      // readers of buffer fbuf (iter it-1) are done
        if (it + 2 < NIT)
            G_FILL(sb + fbuf * STAGE_SZ, (it + 2) * 32);
        CPCOMMIT();
        CPWAIT2();            // stage `it` landed (<=2 fills may stay pending)

        const uint32_t tb = sb + buf * STAGE_SZ;
#pragma unroll
        for (int kk = 0; kk < 2; ++kk) {
            uint32_t ah[2][4], al[2][4], bh[4][4], bl[4][4];
#pragma unroll
            for (int mt = 0; mt < 2; ++mt) {
                uint32_t o = abase + mt * 1024 + aswz[kk];
                LDSM4(ah[mt], tb + o);
                LDSM4(al[mt], tb + TILE_SZ + o);
            }
#pragma unroll
            for (int nt = 0; nt < 4; ++nt) {
                uint32_t o = bbase + nt * 1024 + bswz[kk];
                LDSM4(bh[nt], tb + 2 * TILE_SZ + o);
                LDSM4(bl[nt], tb + 3 * TILE_SZ + o);
            }
#pragma unroll
            for (int p = 0; p < 3; ++p)
#pragma unroll
                for (int mt = 0; mt < 2; ++mt)
#pragma unroll
                    for (int nt = 0; nt < 4; ++nt)
#pragma unroll
                        for (int h = 0; h < 2; ++h) {
                            const uint32_t* A = (p == 2) ? al[mt] : ah[mt];
                            const uint32_t* B = (p == 1) ? bl[nt] : bh[nt];
                            MMA16816(acc[mt][nt * 2 + h], A, B[h], B[h + 2]);
                        }
        }
        buf = (buf == 2) ? 0 : buf + 1;
        fbuf = (fbuf == 2) ? 0 : fbuf + 1;
    }
    CPWAIT0();
#undef G_FILL
}

// ---------------------------------------------------------------------------
// Kernel 1: QKV GEMM.  Epilogue scatters bf16 hi/lo into [t][bh][d][n] and
// emits per-(row, m-tile) sum-of-squares partials for q,k (norm fusion).
// ---------------------------------------------------------------------------
__global__ __launch_bounds__(256) void qkv_mma_kernel() {
    extern __shared__ __align__(128) char sm[];
    const int tid = threadIdx.x, l = tid & 31, w = tid >> 5;
    const int wm = w & 3, wn = w >> 2;
    const int j0 = blockIdx.x * 128, m0 = blockIdx.y * 128;

    GemmCtx g;
    g.Ahi = g_x_hi;  g.Alo = g_x_lo;  g.arow = (size_t)m0;
    g.Bhi = g_wq_hi; g.Blo = g_wq_lo; g.brow = (size_t)j0;

    float acc[2][8][4];
    gemm_mainloop(sm, g, acc);

    float* stage = (float*)sm;     // 64 x 132 floats
    const int b = m0 >> 12, nb = m0 & (Nn - 1);
#pragma unroll
    for (int c = 0; c < 2; ++c) {
        __syncthreads();
        if (wn == c) {
#pragma unroll
            for (int mt = 0; mt < 2; ++mt)
#pragma unroll
                for (int ni = 0; ni < 8; ++ni) {
                    int nt = ni >> 1, h = ni & 1;
                    int jl = nt * 16 + h * 8 + (l & 3) * 2;
                    int ml = wm * 32 + mt * 16 + (l >> 2);
                    const float* d = acc[mt][ni];
                    stage[jl * 132 + ml] = d[0];
                    stage[(jl + 1) * 132 + ml] = d[1];
                    stage[jl * 132 + ml + 8] = d[2];
                    stage[(jl + 1) * 132 + ml + 8] = d[3];
                }
        }
        __syncthreads();
        {
            int jl = tid >> 2, f4 = tid & 3;
            int j = j0 + c * 64 + jl;
            int t = j / Cc, r = j - t * Cc;
            size_t base = ((size_t)t * ROWS + b * Cc + r) * Nn + nb;
            float sq = 0.f;
#pragma unroll
            for (int i = 0; i < 8; ++i) {
                int idx = f4 + i * 4;
                float4 v = *(float4*)(stage + jl * 132 + idx * 4);
                sq = fmaf(v.x, v.x, sq); sq = fmaf(v.y, v.y, sq);
                sq = fmaf(v.z, v.z, sq); sq = fmaf(v.w, v.w, sq);
                uint2 h2, l2;
                split2(v.x, v.y, h2.x, l2.x);
                split2(v.z, v.w, h2.y, l2.y);
                *(uint2*)(g_qkvh + base + idx * 4) = h2;
                *(uint2*)(g_qkvl + base + idx * 4) = l2;
            }
            // norm partials for q,k rows (deterministic, no atomics)
            sq += __shfl_xor_sync(0xffffffffu, sq, 1);
            sq += __shfl_xor_sync(0xffffffffu, sq, 2);
            if (t < 2 && f4 == 0)
                g_nsq[((size_t)t * ROWS + b * Cc + r) * 32 + (nb >> 7)] = sq;
        }
    }
}

// ---------------------------------------------------------------------------
// Kernel 2: reduce norm partials -> inverse norms.  One warp per row.
// ---------------------------------------------------------------------------
__global__ __launch_bounds__(256) void nsq_reduce_kernel() {
    int row = blockIdx.x * 8 + (threadIdx.x >> 5);
    int lane = threadIdx.x & 31;
    float s = g_nsq[(size_t)row * 32 + lane];
#pragma unroll
    for (int o = 16; o; o >>= 1) s += __shfl_xor_sync(0xffffffffu, s, o);
    if (lane == 0)
        g_inv[row] = 1.0f / fmaxf(sqrtf(s), 1e-12f);
}

// ---------------------------------------------------------------------------
// Kernel 6: proj GEMM.  out = ctx @ Wp^T + bias, row-major epilogue.
// ---------------------------------------------------------------------------
__global__ __launch_bounds__(256) void proj_mma_kernel(
    const float* __restrict__ bias, float* __restrict__ out) {
    extern __shared__ __align__(128) char sm[];
    const int tid = threadIdx.x, l = tid & 31, w = tid >> 5;
    const int wm = w & 3, wn = w >> 2;
    const int j0 = blockIdx.x * 128, m0 = blockIdx.y * 128;

    GemmCtx g;
    g.Ahi = g_ctx_hi; g.Alo = g_ctx_lo; g.arow = (size_t)m0;
    g.Bhi = g_wp_hi;  g.Blo = g_wp_lo;  g.brow = (size_t)j0;

    float acc[2][8][4];
    gemm_mainloop(sm, g, acc);

    float* stage = (float*)sm;     // 128 x 68 floats
#pragma unroll
    for (int c = 0; c < 2; ++c) {
        __syncthreads();
        if (wn == c) {
#pragma unroll
            for (int mt = 0; mt < 2; ++mt)
#pragma unroll
                for (int ni = 0; ni < 8; ++ni) {
                    int nt = ni >> 1, h = ni & 1;
                    int jl = nt * 16 + h * 8 + (l & 3) * 2;
                    int ml = wm * 32 + mt * 16 + (l >> 2);
                    const float* d = acc[mt][ni];
                    stage[ml * 68 + jl] = d[0];
                    stage[ml * 68 + jl + 1] = d[1];
                    stage[(ml + 8) * 68 + jl] = d[2];
                    stage[(ml + 8) * 68 + jl + 1] = d[3];
                }
        }
        __syncthreads();
        {
            int ml = tid >> 1, half = tid & 1;
            int jb = j0 + c * 64 + half * 32;
#pragma unroll
            for (int i = 0; i < 8; ++i) {
                float4 v = *(float4*)(stage + ml * 68 + half * 32 + i * 4);
                float4 bb = *(const float4*)(bias + jb + i * 4);
                v.x += bb.x; v.y += bb.y; v.z += bb.z; v.w += bb.w;
                *(float4*)(out + (size_t)(m0 + ml) * Cc + jb + i * 4) = v;
            }
        }
    }
}

// ---------------------------------------------------------------------------
// Kernel 3: attention gram via HMMA (3-pass, relaxed pipeline).
// ---------------------------------------------------------------------------
__global__ __launch_bounds__(192) void attn_part_kernel() {
    extern __shared__ __align__(128) char sm[];
    const int tid = threadIdx.x, l = tid & 31, wm = tid >> 5;   // wm 0..5
    const int bh = blockIdx.x, ch = blockIdx.y;
    const int n0 = ch * (Nn / ACHUNK);                          // chunk of 512
    const uint32_t sb = (uint32_t)__cvta_generic_to_shared(sm);

    const int pr = tid % 96, pc = tid / 96;
    const uint32_t po = (uint32_t)(pr * 48 + pc * 16);
    const size_t qsrc = ((size_t)bh * HD + pr) * Nn + n0 + pc * 8;
    const size_t ksrc = ((size_t)ROWS + (size_t)bh * HD + pr) * Nn + n0 + pc * 8;

    const int lr = l & 15, hsel = l >> 4;
    const uint32_t aoff = (uint32_t)((wm * 16 + lr) * 48 + hsel * 16);
    const uint32_t boff = (uint32_t)(lr * 48 + hsel * 16);

    float acc[12][4];
#pragma unroll
    for (int i = 0; i < 12; ++i)
#pragma unroll
        for (int q = 0; q < 4; ++q) acc[i][q] = 0.f;

    const int NIT = (Nn / ACHUNK) / 16;    // 32

#define A_FILL(DB, KT) do {                                                   \
        CP16((DB) + po,               g_qkvh + qsrc + (KT));                  \
        CP16((DB) + AT_TILE + po,     g_qkvl + qsrc + (KT));                  \
        CP16((DB) + 2 * AT_TILE + po, g_qkvh + ksrc + (KT));                  \
        CP16((DB) + 3 * AT_TILE + po, g_qkvl + ksrc + (KT));                  \
    } while (0)

#pragma unroll
    for (int s = 0; s < 2; ++s) {
        A_FILL(sb + s * AT_STAGE, s * 16);
        CPCOMMIT();
    }

    int buf = 0, fbuf = 2;
    for (int it = 0; it < NIT; ++it) {
        __syncthreads();
        if (it + 2 < NIT)
            A_FILL(sb + fbuf * AT_STAGE, (it + 2) * 16);
        CPCOMMIT();
        CPWAIT2();

        const uint32_t tb = sb + buf * AT_STAGE;
        uint32_t ah[4], al[4], bhf[6][4], blf[6][4];
        LDSM4(ah, tb + aoff);
        LDSM4(al, tb + AT_TILE + aoff);
#pragma unroll
        for (int nt = 0; nt < 6; ++nt) {
            uint32_t o = boff + nt * (16 * 48);
            LDSM4(bhf[nt], tb + 2 * AT_TILE + o);
            LDSM4(blf[nt], tb + 3 * AT_TILE + o);
        }
#pragma unroll
        for (int p = 0; p < 3; ++p)
#pragma unroll
            for (int nt = 0; nt < 6; ++nt)
#pragma unroll
                for (int h = 0; h < 2; ++h) {
                    const uint32_t* A = (p == 2) ? al : ah;
                    const uint32_t* B = (p == 1) ? blf[nt] : bhf[nt];
                    MMA16816(acc[nt * 2 + h], A, B[h], B[h + 2]);
                }
        buf = (buf == 2) ? 0 : buf + 1;
        fbuf = (fbuf == 2) ? 0 : fbuf + 1;
    }
    CPWAIT0();
#undef A_FILL

    float* op = g_attn_part + ((size_t)ch * BH + bh) * (HD * HD);
    const int r0 = wm * 16 + (l >> 2), cb = (l & 3) * 2;
#pragma unroll
    for (int nt = 0; nt < 6; ++nt)
#pragma unroll
        for (int h = 0; h < 2; ++h) {
            int col = nt * 16 + h * 8 + cb;
            const float* c = acc[nt * 2 + h];
            *(float2*)(op + r0 * HD + col) = make_float2(c[0], c[1]);
            *(float2*)(op + (r0 + 8) * HD + col) = make_float2(c[2], c[3]);
        }
}

// ---------------------------------------------------------------------------
// Kernel 4: reduce + scale + softmax
// ---------------------------------------------------------------------------
__global__ __launch_bounds__(128) void softmax_kernel(const float* __restrict__ temperature) {
    int row = blockIdx.x;
    int bh = row / HD;
    int h = bh & (Hh - 1);
    int tid = threadIdx.x;

    float v = -1e30f;
    if (tid < HD) {
        float s = 0.f;
#pragma unroll
        for (int c = 0; c < ACHUNK; ++c)
            s += g_attn_part[((size_t)c * ROWS + row) * HD + tid];
        s *= g_inv[row] * g_inv[ROWS + bh * HD + tid] * temperature[h];
        v = s;
    }
    __shared__ float red[4];
    float m = v;
#pragma unroll
    for (int o = 16; o; o >>= 1) m = fmaxf(m, __shfl_xor_sync(0xffffffffu, m, o));
    if ((tid & 31) == 0) red[tid >> 5] = m;
    __syncthreads();
    m = fmaxf(fmaxf(red[0], red[1]), fmaxf(red[2], red[3]));
    float e = (tid < HD) ? expf(v - m) : 0.f;
    __syncthreads();
    float s2 = e;
#pragma unroll
    for (int o = 16; o; o >>= 1) s2 += __shfl_xor_sync(0xffffffffu, s2, o);
    if ((tid & 31) == 0) red[tid >> 5] = s2;
    __syncthreads();
    float denom = red[0] + red[1] + red[2] + red[3];
    if (tid < HD) g_attn[(size_t)row * HD + tid] = e / denom;
}

// ---------------------------------------------------------------------------
// Kernel 5: ctx = attn @ v via HMMA (3-pass hi/lo).
// ---------------------------------------------------------------------------
__global__ __launch_bounds__(192) void ctx_kernel() {
    extern __shared__ __align__(128) char sm[];
    const int tid = threadIdx.x, l = tid & 31, wm = tid >> 5;   // wm 0..5
    const int bh = blockIdx.x, n0 = blockIdx.y * 128;
    const uint32_t sb = (uint32_t)__cvta_generic_to_shared(sm);

    const size_t vbase = (2ull * ROWS + (size_t)bh * HD) * Nn + n0;
#pragma unroll
    for (int k = 0; k < 8; ++k) {
        int c = tid + k * 192;
        int r = c >> 4, chk = c & 15;
        uint32_t dst = sb + CV_HI + r * 272 + chk * 16;
        CP16(dst, g_qkvh + vbase + (size_t)r * Nn + chk * 8);
        CP16(dst + (CV_LO - CV_HI), g_qkvl + vbase + (size_t)r * Nn + chk * 8);
    }
    CPCOMMIT();

    {
        const float* ap = g_attn + (size_t)bh * HD * HD;
        __nv_bfloat16* Ahp = (__nv_bfloat16*)(sm + CA_HI);
        __nv_bfloat16* Alp = (__nv_bfloat16*)(sm + CA_LO);
        for (int i = tid; i < HD * HD; i += 192) {
            int d = i / HD, e = i - d * HD;
            float v = ap[i];
            __nv_bfloat16 hi = __float2bfloat16(v);
            __nv_bfloat16 lo = __float2bfloat16(v - __bfloat162float(hi));
            Ahp[d * 104 + e] = hi;
            Alp[d * 104 + e] = lo;
        }
    }
    CPWAIT0();
    __syncthreads();

    float acc[16][4];
#pragma unroll
    for (int i = 0; i < 16; ++i)
#pragma unroll
        for (int q = 0; q < 4; ++q) acc[i][q] = 0.f;

    const int lr = l & 15, hsel = l >> 4;
    const uint32_t aoff = sb + CA_HI + (uint32_t)((wm * 16 + lr) * 208 + hsel * 16);
    const int be = (l & 7) + ((l >> 4) << 3);
    const uint32_t boff = sb + CV_HI + (uint32_t)(be * 272 + ((l >> 3) & 1) * 16);

#pragma unroll
    for (int kc = 0; kc < 6; ++kc) {
        uint32_t ah[4], al[4];
        LDSM4(ah, aoff + kc * 32);
        LDSM4(al, aoff + (CA_LO - CA_HI) + kc * 32);
#pragma unroll
        for (int nq = 0; nq < 8; ++nq) {
            uint32_t bhf[4], blf[4];
            uint32_t o = boff + (uint32_t)(kc * 16 * 272 + nq * 32);
            LDSM4T(bhf, o);
            LDSM4T(blf, o + (CV_LO - CV_HI));
#pragma unroll
            for (int p = 0; p < 3; ++p)
#pragma unroll
                for (int h = 0; h < 2; ++h) {
                    const uint32_t* A = (p == 2) ? al : ah;
                    const uint32_t* B = (p == 1) ? blf : bhf;
                    MMA16816(acc[nq * 2 + h], A, B[h], B[h + 2]);
                }
        }
    }

    __syncthreads();
    float* stage = (float*)sm;
    {
        const int d0 = wm * 16 + (l >> 2), cb = (l & 3) * 2;
#pragma unroll
        for (int nq = 0; nq < 8; ++nq)
#pragma unroll
            for (int h = 0; h < 2; ++h) {
                int n = nq * 16 + h * 8 + cb;
                const float* c = acc[nq * 2 + h];
                stage[n * 100 + d0] = c[0];
                stage[(n + 1) * 100 + d0] = c[1];
                stage[n * 100 + d0 + 8] = c[2];
                stage[(n + 1) * 100 + d0 + 8] = c[3];
            }
    }
    __syncthreads();
    {
        const int b = bh >> 3, hh = bh & 7;
#pragma unroll
        for (int k = 0; k < 32; ++k) {
            int flat = tid + k * 192;
            int n = flat / 48, j = flat - n * 48;
            float v0 = stage[n * 100 + j * 2];
            float v1 = stage[n * 100 + j * 2 + 1];
            uint32_t hi, lo;
            split2(v0, v1, hi, lo);
            size_t addr = ((size_t)(b * Nn + n0 + n)) * Cc + hh * HD + j * 2;
            *(uint32_t*)(g_ctx_hi + addr) = hi;
            *(uint32_t*)(g_ctx_lo + addr) = lo;
        }
    }
}

// ---------------------------------------------------------------------------
// Launcher
// ---------------------------------------------------------------------------
extern "C" void kernel_launch(void* const* d_in, const int* in_sizes, int n_in,
                              void* d_out, int out_size) {
    const float* x      = (const float*)d_in[0];
    const float* w_qkv  = (const float*)d_in[1];
    const float* temp   = (const float*)d_in[2];
    const float* w_proj = (const float*)d_in[3];
    const float* b_proj = (const float*)d_in[4];
    float* out = (float*)d_out;

    __nv_bfloat16 *xh, *xl, *qh, *ql, *ph, *pl;
    cudaGetSymbolAddress((void**)&xh, g_x_hi);
    cudaGetSymbolAddress((void**)&xl, g_x_lo);
    cudaGetSymbolAddress((void**)&qh, g_wq_hi);
    cudaGetSymbolAddress((void**)&ql, g_wq_lo);
    cudaGetSymbolAddress((void**)&ph, g_wp_hi);
    cudaGetSymbolAddress((void**)&pl, g_wp_lo);

    cudaFuncSetAttribute(qkv_mma_kernel,
                         cudaFuncAttributeMaxDynamicSharedMemorySize, SMEM_GEMM);
    cudaFuncSetAttribute(proj_mma_kernel,
                         cudaFuncAttributeMaxDynamicSharedMemorySize, SMEM_GEMM);
    cudaFuncSetAttribute(attn_part_kernel,
                         cudaFuncAttributeMaxDynamicSharedMemorySize, SMEM_ATT);
    cudaFuncSetAttribute(ctx_kernel,
                         cudaFuncAttributeMaxDynamicSharedMemorySize, SMEM_CTX);

    const int nx = M1 * Cc / 4, nq = 3 * Cc * Cc / 4, np = Cc * Cc / 4;
    split_kernel<<<(nx + 255) / 256, 256>>>(x, xh, xl, nx);
    split_kernel<<<(nq + 255) / 256, 256>>>(w_qkv, qh, ql, nq);
    split_kernel<<<(np + 255) / 256, 256>>>(w_proj, ph, pl, np);

    qkv_mma_kernel<<<dim3(3 * Cc / 128, M1 / 128), 256, SMEM_GEMM>>>();
    nsq_reduce_kernel<<<2 * ROWS / 8, 256>>>();
    attn_part_kernel<<<dim3(BH, ACHUNK), 192, SMEM_ATT>>>();
    softmax_kernel<<<ROWS, 128>>>(temp);
    ctx_kernel<<<dim3(BH, Nn / 128), 192, SMEM_CTX>>>();
    proj_mma_kernel<<<dim3(Cc / 128, M1 / 128), 256, SMEM_GEMM>>>(b_proj, out);
}

// round 10
// speedup vs baseline: 1.8406x; 1.3420x over previous
#include <cuda_runtime.h>
#include <cuda_bf16.h>
#include <cuda_fp16.h>
#include <math.h>
#include <cstdint>

// Problem constants
#define Bz   8
#define Nn   4096
#define Cc   768
#define Hh   8
#define HD   96
#define M1   (Bz * Nn)          // 32768 tokens
#define BH   (Bz * Hh)          // 64
#define ROWS (BH * HD)          // 6144 rows per tensor (q or k)
#define ACHUNK 8                // split-K chunks for attention gram

// ---------------------------------------------------------------------------
// Device scratch
// ---------------------------------------------------------------------------
__device__ __nv_bfloat16 g_qkvh[3ull * ROWS * Nn];   // attn path, bf16 hi
__device__ __nv_bfloat16 g_qkvl[3ull * ROWS * Nn];   // attn path, bf16 lo
__device__ float g_nsq[2 * ROWS * 32];
__device__ float g_inv[2 * ROWS];
__device__ float g_attn_part[(size_t)ACHUNK * BH * HD * HD];
__device__ float g_attn[(size_t)BH * HD * HD];
__device__ __half g_ctx_h[(size_t)M1 * Cc];          // ctx [m][c], fp16 hi only
__device__ __half g_x_h[(size_t)M1 * Cc];            // X fp16 (hi only)
__device__ __half g_wq_h[3 * Cc * Cc];
__device__ __half g_wq_l[3 * Cc * Cc];
__device__ __half g_wp_h[Cc * Cc];
__device__ __half g_wp_l[Cc * Cc];

// ---------------------------------------------------------------------------
// PTX helpers (baseline target: mma.sync + ldmatrix + cp.async only)
// ---------------------------------------------------------------------------
#define LDSM4(R, A)                                                           \
    asm volatile("ldmatrix.sync.aligned.m8n8.x4.shared.b16 {%0,%1,%2,%3}, [%4];" \
        : "=r"((R)[0]), "=r"((R)[1]), "=r"((R)[2]), "=r"((R)[3]) : "r"(A))

#define LDSM4T(R, A)                                                          \
    asm volatile("ldmatrix.sync.aligned.m8n8.x4.trans.shared.b16 {%0,%1,%2,%3}, [%4];" \
        : "=r"((R)[0]), "=r"((R)[1]), "=r"((R)[2]), "=r"((R)[3]) : "r"(A))

#define MMA_BF(C, A, B0, B1)                                                  \
    asm volatile("mma.sync.aligned.m16n8k16.row.col.f32.bf16.bf16.f32 "       \
        "{%0,%1,%2,%3}, {%4,%5,%6,%7}, {%8,%9}, {%0,%1,%2,%3};"               \
        : "+f"((C)[0]), "+f"((C)[1]), "+f"((C)[2]), "+f"((C)[3])              \
        : "r"((A)[0]), "r"((A)[1]), "r"((A)[2]), "r"((A)[3]), "r"(B0), "r"(B1))

#define MMA_FP(C, A, B0, B1)                                                  \
    asm volatile("mma.sync.aligned.m16n8k16.row.col.f32.f16.f16.f32 "         \
        "{%0,%1,%2,%3}, {%4,%5,%6,%7}, {%8,%9}, {%0,%1,%2,%3};"               \
        : "+f"((C)[0]), "+f"((C)[1]), "+f"((C)[2]), "+f"((C)[3])              \
        : "r"((A)[0]), "r"((A)[1]), "r"((A)[2]), "r"((A)[3]), "r"(B0), "r"(B1))

#define CP16(d, s)                                                            \
    asm volatile("cp.async.cg.shared.global [%0], [%1], 16;" :: "r"(d), "l"(s))
#define CPCOMMIT() asm volatile("cp.async.commit_group;" ::: "memory")
#define CPWAIT3()  asm volatile("cp.async.wait_group 3;" ::: "memory")
#define CPWAIT2()  asm volatile("cp.async.wait_group 2;" ::: "memory")
#define CPWAIT0()  asm volatile("cp.async.wait_group 0;" ::: "memory")

__device__ __forceinline__ void split2bf(float x, float y, uint32_t& hi, uint32_t& lo) {
    __nv_bfloat16 hx = __float2bfloat16(x), hy = __float2bfloat16(y);
    __nv_bfloat16 lx = __float2bfloat16(x - __bfloat162float(hx));
    __nv_bfloat16 ly = __float2bfloat16(y - __bfloat162float(hy));
    hi = (uint32_t)__bfloat16_as_ushort(hx) | ((uint32_t)__bfloat16_as_ushort(hy) << 16);
    lo = (uint32_t)__bfloat16_as_ushort(lx) | ((uint32_t)__bfloat16_as_ushort(ly) << 16);
}

// Main GEMM smem pipeline (fp16 2-pass): tile = 128 rows x 64B swizzled = 8KB
// stage = 3 tiles (Ahi, Bhi, Blo) = 24KB ; 4 stages = 96KB (dynamic)
#define TILE_SZ  8192
#define STAGE_SZ 24576
#define SMEM_GEMM (4 * STAGE_SZ)   // 98304

// attn_part smem: tile = 96 rows x 48B = 4608B; stage = 4 tiles; 3 stages
#define AT_TILE  4608
#define AT_STAGE 18432
#define SMEM_ATT (3 * AT_STAGE)

// ctx smem layout: attn hi/lo tiles (96 x 208B) + v hi/lo tiles (96 x 272B)
#define CA_HI 0
#define CA_LO 19968
#define CV_HI 39936
#define CV_LO 66048
#define SMEM_CTX 92160

// ---------------------------------------------------------------------------
// Kernel 0a: fp32 -> fp16 convert (X, hi only)
// ---------------------------------------------------------------------------
__global__ __launch_bounds__(256) void cvt_h_kernel(
    const float* __restrict__ src, __half* __restrict__ dst, int n4) {
    int i = blockIdx.x * 256 + threadIdx.x;
    if (i < n4) {
        float4 v = ((const float4*)src)[i];
        __half2 a = __floats2half2_rn(v.x, v.y);
        __half2 b = __floats2half2_rn(v.z, v.w);
        ((__half2*)dst)[i * 2] = a;
        ((__half2*)dst)[i * 2 + 1] = b;
    }
}

// ---------------------------------------------------------------------------
// Kernel 0b: fp32 -> fp16 hi/lo split (weights)
// ---------------------------------------------------------------------------
__global__ __launch_bounds__(256) void split_h_kernel(
    const float* __restrict__ src, __half* __restrict__ hi,
    __half* __restrict__ lo, int n4) {
    int i = blockIdx.x * 256 + threadIdx.x;
    if (i < n4) {
        float4 v = ((const float4*)src)[i];
        __half hx = __float2half_rn(v.x), hy = __float2half_rn(v.y);
        __half hz = __float2half_rn(v.z), hw = __float2half_rn(v.w);
        __half lx = __float2half_rn(v.x - __half2float(hx));
        __half ly = __float2half_rn(v.y - __half2float(hy));
        __half lz = __float2half_rn(v.z - __half2float(hz));
        __half lw = __float2half_rn(v.w - __half2float(hw));
        ((__half2*)hi)[i * 2] = __halves2half2(hx, hy);
        ((__half2*)hi)[i * 2 + 1] = __halves2half2(hz, hw);
        ((__half2*)lo)[i * 2] = __halves2half2(lx, ly);
        ((__half2*)lo)[i * 2 + 1] = __halves2half2(lz, lw);
    }
}

// ---------------------------------------------------------------------------
// Main GEMM mainloop: 128x128 CTA tile, K-step 32, 4-stage cp.async,
// fp16 2-pass: C = Ahi*Bhi + Ahi*Blo.  8 warps (4M x 2N).
// Swizzle: smem offset(r, chunk) = r*64 + ((chunk ^ ((r>>1)&3)) << 4)
// ---------------------------------------------------------------------------
struct GemmCtx {
    const __half *Ah, *Bh, *Bl;   // row-major [*, Cc]
    size_t arow, brow;
};

__device__ __forceinline__ void gemm_mainloop(
    char* sm, const GemmCtx& g, float acc[2][8][4]) {
    const int tid = threadIdx.x, l = tid & 31, w = tid >> 5;
    const int wm = w & 3, wn = w >> 2;
    const uint32_t sb = (uint32_t)__cvta_generic_to_shared(sm);

    const int pr = tid >> 1, pc0 = (tid & 1) * 2;
    const int prx = (pr >> 1) & 3;
    const uint32_t po0 = (uint32_t)(pr * 64 + ((pc0 ^ prx) << 4));
    const uint32_t po1 = (uint32_t)(pr * 64 + (((pc0 + 1) ^ prx) << 4));
    const size_t asrc = (g.arow + pr) * Cc + pc0 * 8;
    const size_t bsrc = (g.brow + pr) * Cc + pc0 * 8;

    const int lr = l & 15, hsel = l >> 4;
    const int rowA = wm * 32 + lr, rowB = wn * 64 + lr;
    const int rxa = (rowA >> 1) & 3, rxb = (rowB >> 1) & 3;
    const uint32_t aswz[2] = { (uint32_t)((hsel ^ rxa) << 4),
                               (uint32_t)(((2 + hsel) ^ rxa) << 4) };
    const uint32_t bswz[2] = { (uint32_t)((hsel ^ rxb) << 4),
                               (uint32_t)(((2 + hsel) ^ rxb) << 4) };
    const uint32_t abase = (uint32_t)(rowA * 64);
    const uint32_t bbase = (uint32_t)(rowB * 64);

#pragma unroll
    for (int mt = 0; mt < 2; ++mt)
#pragma unroll
        for (int ni = 0; ni < 8; ++ni)
#pragma unroll
            for (int q = 0; q < 4; ++q) acc[mt][ni][q] = 0.f;

    const int NIT = Cc / 32;    // 24

#define G_FILL(DB, KT) do {                                                   \
        CP16((DB) + po0,               g.Ah + asrc + (KT));                   \
        CP16((DB) + po1,               g.Ah + asrc + (KT) + 8);               \
        CP16((DB) + TILE_SZ + po0,     g.Bh + bsrc + (KT));                   \
        CP16((DB) + TILE_SZ + po1,     g.Bh + bsrc + (KT) + 8);               \
        CP16((DB) + 2 * TILE_SZ + po0, g.Bl + bsrc + (KT));                   \
        CP16((DB) + 2 * TILE_SZ + po1, g.Bl + bsrc + (KT) + 8);               \
    } while (0)

#pragma unroll
    for (int s = 0; s < 3; ++s) {
        G_FILL(sb + s * STAGE_SZ, s * 32);
        CPCOMMIT();
    }

    int buf = 0, fbuf = 3;
    for (int it = 0; it < NIT; ++it) {
        __syncthreads();      // readers of buffer fbuf (iter it-1) are done
        if (it + 3 < NIT)
            G_FILL(sb + fbuf * STAGE_SZ, (it + 3) * 32);
        CPCOMMIT();
        CPWAIT3();            // stage `it` landed (<=3 fills may stay pending)

        const uint32_t tb = sb + buf * STAGE_SZ;
#pragma unroll
        for (int kk = 0; kk < 2; ++kk) {
            uint32_t ah[2][4], bh[4][4], bl[4][4];
#pragma unroll
            for (int mt = 0; mt < 2; ++mt)
                LDSM4(ah[mt], tb + abase + mt * 1024 + aswz[kk]);
#pragma unroll
            for (int nt = 0; nt < 4; ++nt) {
                uint32_t o = bbase + nt * 1024 + bswz[kk];
                LDSM4(bh[nt], tb + TILE_SZ + o);
                LDSM4(bl[nt], tb + 2 * TILE_SZ + o);
            }
#pragma unroll
            for (int p = 0; p < 2; ++p)
#pragma unroll
                for (int mt = 0; mt < 2; ++mt)
#pragma unroll
                    for (int nt = 0; nt < 4; ++nt)
#pragma unroll
                        for (int h = 0; h < 2; ++h) {
                            const uint32_t* B = (p == 1) ? bl[nt] : bh[nt];
                            MMA_FP(acc[mt][nt * 2 + h], ah[mt], B[h], B[h + 2]);
                        }
        }
        buf = (buf + 1) & 3;
        fbuf = (fbuf + 1) & 3;
    }
    CPWAIT0();
#undef G_FILL
}

// ---------------------------------------------------------------------------
// Kernel 1: QKV GEMM.  Epilogue scatters bf16 hi/lo into [t][bh][d][n] and
// emits per-(row, m-tile) sum-of-squares partials for q,k (norm fusion).
// ---------------------------------------------------------------------------
__global__ __launch_bounds__(256) void qkv_mma_kernel() {
    extern __shared__ __align__(128) char sm[];
    const int tid = threadIdx.x, l = tid & 31, w = tid >> 5;
    const int wm = w & 3, wn = w >> 2;
    const int j0 = blockIdx.x * 128, m0 = blockIdx.y * 128;

    GemmCtx g;
    g.Ah = g_x_h;  g.arow = (size_t)m0;
    g.Bh = g_wq_h; g.Bl = g_wq_l; g.brow = (size_t)j0;

    float acc[2][8][4];
    gemm_mainloop(sm, g, acc);

    float* stage = (float*)sm;     // 64 x 132 floats
    const int b = m0 >> 12, nb = m0 & (Nn - 1);
#pragma unroll
    for (int c = 0; c < 2; ++c) {
        __syncthreads();
        if (wn == c) {
#pragma unroll
            for (int mt = 0; mt < 2; ++mt)
#pragma unroll
                for (int ni = 0; ni < 8; ++ni) {
                    int nt = ni >> 1, h = ni & 1;
                    int jl = nt * 16 + h * 8 + (l & 3) * 2;
                    int ml = wm * 32 + mt * 16 + (l >> 2);
                    const float* d = acc[mt][ni];
                    stage[jl * 132 + ml] = d[0];
                    stage[(jl + 1) * 132 + ml] = d[1];
                    stage[jl * 132 + ml + 8] = d[2];
                    stage[(jl + 1) * 132 + ml + 8] = d[3];
                }
        }
        __syncthreads();
        {
            int jl = tid >> 2, f4 = tid & 3;
            int j = j0 + c * 64 + jl;
            int t = j / Cc, r = j - t * Cc;
            size_t base = ((size_t)t * ROWS + b * Cc + r) * Nn + nb;
            float sq = 0.f;
#pragma unroll
            for (int i = 0; i < 8; ++i) {
                int idx = f4 + i * 4;
                float4 v = *(float4*)(stage + jl * 132 + idx * 4);
                sq = fmaf(v.x, v.x, sq); sq = fmaf(v.y, v.y, sq);
                sq = fmaf(v.z, v.z, sq); sq = fmaf(v.w, v.w, sq);
                uint2 h2, l2;
                split2bf(v.x, v.y, h2.x, l2.x);
                split2bf(v.z, v.w, h2.y, l2.y);
                *(uint2*)(g_qkvh + base + idx * 4) = h2;
                *(uint2*)(g_qkvl + base + idx * 4) = l2;
            }
            sq += __shfl_xor_sync(0xffffffffu, sq, 1);
            sq += __shfl_xor_sync(0xffffffffu, sq, 2);
            if (t < 2 && f4 == 0)
                g_nsq[((size_t)t * ROWS + b * Cc + r) * 32 + (nb >> 7)] = sq;
        }
    }
}

// ---------------------------------------------------------------------------
// Kernel 2: reduce norm partials -> inverse norms.  One warp per row.
// ---------------------------------------------------------------------------
__global__ __launch_bounds__(256) void nsq_reduce_kernel() {
    int row = blockIdx.x * 8 + (threadIdx.x >> 5);
    int lane = threadIdx.x & 31;
    float s = g_nsq[(size_t)row * 32 + lane];
#pragma unroll
    for (int o = 16; o; o >>= 1) s += __shfl_xor_sync(0xffffffffu, s, o);
    if (lane == 0)
        g_inv[row] = 1.0f / fmaxf(sqrtf(s), 1e-12f);
}

// ---------------------------------------------------------------------------
// Kernel 6: proj GEMM.  out = ctx @ Wp^T + bias, row-major epilogue.
// ---------------------------------------------------------------------------
__global__ __launch_bounds__(256) void proj_mma_kernel(
    const float* __restrict__ bias, float* __restrict__ out) {
    extern __shared__ __align__(128) char sm[];
    const int tid = threadIdx.x, l = tid & 31, w = tid >> 5;
    const int wm = w & 3, wn = w >> 2;
    const int j0 = blockIdx.x * 128, m0 = blockIdx.y * 128;

    GemmCtx g;
    g.Ah = g_ctx_h; g.arow = (size_t)m0;
    g.Bh = g_wp_h;  g.Bl = g_wp_l;  g.brow = (size_t)j0;

    float acc[2][8][4];
    gemm_mainloop(sm, g, acc);

    float* stage = (float*)sm;     // 128 x 68 floats
#pragma unroll
    for (int c = 0; c < 2; ++c) {
        __syncthreads();
        if (wn == c) {
#pragma unroll
            for (int mt = 0; mt < 2; ++mt)
#pragma unroll
                for (int ni = 0; ni < 8; ++ni) {
                    int nt = ni >> 1, h = ni & 1;
                    int jl = nt * 16 + h * 8 + (l & 3) * 2;
                    int ml = wm * 32 + mt * 16 + (l >> 2);
                    const float* d = acc[mt][ni];
                    stage[ml * 68 + jl] = d[0];
                    stage[ml * 68 + jl + 1] = d[1];
                    stage[(ml + 8) * 68 + jl] = d[2];
                    stage[(ml + 8) * 68 + jl + 1] = d[3];
                }
        }
        __syncthreads();
        {
            int ml = tid >> 1, half = tid & 1;
            int jb = j0 + c * 64 + half * 32;
#pragma unroll
            for (int i = 0; i < 8; ++i) {
                float4 v = *(float4*)(stage + ml * 68 + half * 32 + i * 4);
                float4 bb = *(const float4*)(bias + jb + i * 4);
                v.x += bb.x; v.y += bb.y; v.z += bb.z; v.w += bb.w;
                *(float4*)(out + (size_t)(m0 + ml) * Cc + jb + i * 4) = v;
            }
        }
    }
}

// ---------------------------------------------------------------------------
// Kernel 3: attention gram via HMMA (bf16 3-pass, unchanged).
// ---------------------------------------------------------------------------
__global__ __launch_bounds__(192) void attn_part_kernel() {
    extern __shared__ __align__(128) char sm[];
    const int tid = threadIdx.x, l = tid & 31, wm = tid >> 5;   // wm 0..5
    const int bh = blockIdx.x, ch = blockIdx.y;
    const int n0 = ch * (Nn / ACHUNK);
    const uint32_t sb = (uint32_t)__cvta_generic_to_shared(sm);

    const int pr = tid % 96, pc = tid / 96;
    const uint32_t po = (uint32_t)(pr * 48 + pc * 16);
    const size_t qsrc = ((size_t)bh * HD + pr) * Nn + n0 + pc * 8;
    const size_t ksrc = ((size_t)ROWS + (size_t)bh * HD + pr) * Nn + n0 + pc * 8;

    const int lr = l & 15, hsel = l >> 4;
    const uint32_t aoff = (uint32_t)((wm * 16 + lr) * 48 + hsel * 16);
    const uint32_t boff = (uint32_t)(lr * 48 + hsel * 16);

    float acc[12][4];
#pragma unroll
    for (int i = 0; i < 12; ++i)
#pragma unroll
        for (int q = 0; q < 4; ++q) acc[i][q] = 0.f;

    const int NIT = (Nn / ACHUNK) / 16;    // 32

#define A_FILL(DB, KT) do {                                                   \
        CP16((DB) + po,               g_qkvh + qsrc + (KT));                  \
        CP16((DB) + AT_TILE + po,     g_qkvl + qsrc + (KT));                  \
        CP16((DB) + 2 * AT_TILE + po, g_qkvh + ksrc + (KT));                  \
        CP16((DB) + 3 * AT_TILE + po, g_qkvl + ksrc + (KT));                  \
    } while (0)

#pragma unroll
    for (int s = 0; s < 2; ++s) {
        A_FILL(sb + s * AT_STAGE, s * 16);
        CPCOMMIT();
    }

    int buf = 0, fbuf = 2;
    for (int it = 0; it < NIT; ++it) {
        __syncthreads();
        if (it + 2 < NIT)
            A_FILL(sb + fbuf * AT_STAGE, (it + 2) * 16);
        CPCOMMIT();
        CPWAIT2();

        const uint32_t tb = sb + buf * AT_STAGE;
        uint32_t ah[4], al[4], bhf[6][4], blf[6][4];
        LDSM4(ah, tb + aoff);
        LDSM4(al, tb + AT_TILE + aoff);
#pragma unroll
        for (int nt = 0; nt < 6; ++nt) {
            uint32_t o = boff + nt * (16 * 48);
            LDSM4(bhf[nt], tb + 2 * AT_TILE + o);
            LDSM4(blf[nt], tb + 3 * AT_TILE + o);
        }
#pragma unroll
        for (int p = 0; p < 3; ++p)
#pragma unroll
            for (int nt = 0; nt < 6; ++nt)
#pragma unroll
                for (int h = 0; h < 2; ++h) {
                    const uint32_t* A = (p == 2) ? al : ah;
                    const uint32_t* B = (p == 1) ? blf[nt] : bhf[nt];
                    MMA_BF(acc[nt * 2 + h], A, B[h], B[h + 2]);
                }
        buf = (buf == 2) ? 0 : buf + 1;
        fbuf = (fbuf == 2) ? 0 : fbuf + 1;
    }
    CPWAIT0();
#undef A_FILL

    float* op = g_attn_part + ((size_t)ch * BH + bh) * (HD * HD);
    const int r0 = wm * 16 + (l >> 2), cb = (l & 3) * 2;
#pragma unroll
    for (int nt = 0; nt < 6; ++nt)
#pragma unroll
        for (int h = 0; h < 2; ++h) {
            int col = nt * 16 + h * 8 + cb;
            const float* c = acc[nt * 2 + h];
            *(float2*)(op + r0 * HD + col) = make_float2(c[0], c[1]);
            *(float2*)(op + (r0 + 8) * HD + col) = make_float2(c[2], c[3]);
        }
}

// ---------------------------------------------------------------------------
// Kernel 4: reduce + scale + softmax
// ---------------------------------------------------------------------------
__global__ __launch_bounds__(128) void softmax_kernel(const float* __restrict__ temperature) {
    int row = blockIdx.x;
    int bh = row / HD;
    int h = bh & (Hh - 1);
    int tid = threadIdx.x;

    float v = -1e30f;
    if (tid < HD) {
        float s = 0.f;
#pragma unroll
        for (int c = 0; c < ACHUNK; ++c)
            s += g_attn_part[((size_t)c * ROWS + row) * HD + tid];
        s *= g_inv[row] * g_inv[ROWS + bh * HD + tid] * temperature[h];
        v = s;
    }
    __shared__ float red[4];
    float m = v;
#pragma unroll
    for (int o = 16; o; o >>= 1) m = fmaxf(m, __shfl_xor_sync(0xffffffffu, m, o));
    if ((tid & 31) == 0) red[tid >> 5] = m;
    __syncthreads();
    m = fmaxf(fmaxf(red[0], red[1]), fmaxf(red[2], red[3]));
    float e = (tid < HD) ? expf(v - m) : 0.f;
    __syncthreads();
    float s2 = e;
#pragma unroll
    for (int o = 16; o; o >>= 1) s2 += __shfl_xor_sync(0xffffffffu, s2, o);
    if ((tid & 31) == 0) red[tid >> 5] = s2;
    __syncthreads();
    float denom = red[0] + red[1] + red[2] + red[3];
    if (tid < HD) g_attn[(size_t)row * HD + tid] = e / denom;
}

// ---------------------------------------------------------------------------
// Kernel 5: ctx = attn @ v via HMMA (bf16 3-pass); emits fp16 ctx [m][c].
// ---------------------------------------------------------------------------
__global__ __launch_bounds__(192) void ctx_kernel() {
    extern __shared__ __align__(128) char sm[];
    const int tid = threadIdx.x, l = tid & 31, wm = tid >> 5;   // wm 0..5
    const int bh = blockIdx.x, n0 = blockIdx.y * 128;
    const uint32_t sb = (uint32_t)__cvta_generic_to_shared(sm);

    const size_t vbase = (2ull * ROWS + (size_t)bh * HD) * Nn + n0;
#pragma unroll
    for (int k = 0; k < 8; ++k) {
        int c = tid + k * 192;
        int r = c >> 4, chk = c & 15;
        uint32_t dst = sb + CV_HI + r * 272 + chk * 16;
        CP16(dst, g_qkvh + vbase + (size_t)r * Nn + chk * 8);
        CP16(dst + (CV_LO - CV_HI), g_qkvl + vbase + (size_t)r * Nn + chk * 8);
    }
    CPCOMMIT();

    {
        const float* ap = g_attn + (size_t)bh * HD * HD;
        __nv_bfloat16* Ahp = (__nv_bfloat16*)(sm + CA_HI);
        __nv_bfloat16* Alp = (__nv_bfloat16*)(sm + CA_LO);
        for (int i = tid; i < HD * HD; i += 192) {
            int d = i / HD, e = i - d * HD;
            float v = ap[i];
            __nv_bfloat16 hi = __float2bfloat16(v);
            __nv_bfloat16 lo = __float2bfloat16(v - __bfloat162float(hi));
            Ahp[d * 104 + e] = hi;
            Alp[d * 104 + e] = lo;
        }
    }
    CPWAIT0();
    __syncthreads();

    float acc[16][4];
#pragma unroll
    for (int i = 0; i < 16; ++i)
#pragma unroll
        for (int q = 0; q < 4; ++q) acc[i][q] = 0.f;

    const int lr = l & 15, hsel = l >> 4;
    const uint32_t aoff = sb + CA_HI + (uint32_t)((wm * 16 + lr) * 208 + hsel * 16);
    const int be = (l & 7) + ((l >> 4) << 3);
    const uint32_t boff = sb + CV_HI + (uint32_t)(be * 272 + ((l >> 3) & 1) * 16);

#pragma unroll
    for (int kc = 0; kc < 6; ++kc) {
        uint32_t ah[4], al[4];
        LDSM4(ah, aoff + kc * 32);
        LDSM4(al, aoff + (CA_LO - CA_HI) + kc * 32);
#pragma unroll
        for (int nq = 0; nq < 8; ++nq) {
            uint32_t bhf[4], blf[4];
            uint32_t o = boff + (uint32_t)(kc * 16 * 272 + nq * 32);
            LDSM4T(bhf, o);
            LDSM4T(blf, o + (CV_LO - CV_HI));
#pragma unroll
            for (int p = 0; p < 3; ++p)
#pragma unroll
                for (int h = 0; h < 2; ++h) {
                    const uint32_t* A = (p == 2) ? al : ah;
                    const uint32_t* B = (p == 1) ? blf : bhf;
                    MMA_BF(acc[nq * 2 + h], A, B[h], B[h + 2]);
                }
        }
    }

    __syncthreads();
    float* stage = (float*)sm;
    {
        const int d0 = wm * 16 + (l >> 2), cb = (l & 3) * 2;
#pragma unroll
        for (int nq = 0; nq < 8; ++nq)
#pragma unroll
            for (int h = 0; h < 2; ++h) {
                int n = nq * 16 + h * 8 + cb;
                const float* c = acc[nq * 2 + h];
                stage[n * 100 + d0] = c[0];
                stage[(n + 1) * 100 + d0] = c[1];
                stage[n * 100 + d0 + 8] = c[2];
                stage[(n + 1) * 100 + d0 + 8] = c[3];
            }
    }
    __syncthreads();
    {
        const int b = bh >> 3, hh = bh & 7;
#pragma unroll
        for (int k = 0; k < 32; ++k) {
            int flat = tid + k * 192;
            int n = flat / 48, j = flat - n * 48;
            float v0 = stage[n * 100 + j * 2];
            float v1 = stage[n * 100 + j * 2 + 1];
            size_t addr = ((size_t)(b * Nn + n0 + n)) * Cc + hh * HD + j * 2;
            *(__half2*)(g_ctx_h + addr) = __floats2half2_rn(v0, v1);
        }
    }
}

// ---------------------------------------------------------------------------
// Launcher
// ---------------------------------------------------------------------------
extern "C" void kernel_launch(void* const* d_in, const int* in_sizes, int n_in,
                              void* d_out, int out_size) {
    const float* x      = (const float*)d_in[0];
    const float* w_qkv  = (const float*)d_in[1];
    const float* temp   = (const float*)d_in[2];
    const float* w_proj = (const float*)d_in[3];
    const float* b_proj = (const float*)d_in[4];
    float* out = (float*)d_out;

    __half *xh, *qh, *ql, *ph, *pl;
    cudaGetSymbolAddress((void**)&xh, g_x_h);
    cudaGetSymbolAddress((void**)&qh, g_wq_h);
    cudaGetSymbolAddress((void**)&ql, g_wq_l);
    cudaGetSymbolAddress((void**)&ph, g_wp_h);
    cudaGetSymbolAddress((void**)&pl, g_wp_l);

    cudaFuncSetAttribute(qkv_mma_kernel,
                         cudaFuncAttributeMaxDynamicSharedMemorySize, SMEM_GEMM);
    cudaFuncSetAttribute(proj_mma_kernel,
                         cudaFuncAttributeMaxDynamicSharedMemorySize, SMEM_GEMM);
    cudaFuncSetAttribute(attn_part_kernel,
                         cudaFuncAttributeMaxDynamicSharedMemorySize, SMEM_ATT);
    cudaFuncSetAttribute(ctx_kernel,
                         cudaFuncAttributeMaxDynamicSharedMemorySize, SMEM_CTX);

    const int nx = M1 * Cc / 4, nq = 3 * Cc * Cc / 4, np = Cc * Cc / 4;
    cvt_h_kernel<<<(nx + 255) / 256, 256>>>(x, xh, nx);
    split_h_kernel<<<(nq + 255) / 256, 256>>>(w_qkv, qh, ql, nq);
    split_h_kernel<<<(np + 255) / 256, 256>>>(w_proj, ph, pl, np);

    qkv_mma_kernel<<<dim3(3 * Cc / 128, M1 / 128), 256, SMEM_GEMM>>>();
    nsq_reduce_kernel<<<2 * ROWS / 8, 256>>>();
    attn_part_kernel<<<dim3(BH, ACHUNK), 192, SMEM_ATT>>>();
    softmax_kernel<<<ROWS, 128>>>(temp);
    ctx_kernel<<<dim3(BH, Nn / 128), 192, SMEM_CTX>>>();
    proj_mma_kernel<<<dim3(Cc / 128, M1 / 128), 256, SMEM_GEMM>>>(b_proj, out);
}

// round 12
// speedup vs baseline: 2.6993x; 1.4665x over previous
#include <cuda_runtime.h>
#include <cuda_bf16.h>
#include <cuda_fp16.h>
#include <math.h>
#include <cstdint>

// Problem constants
#define Bz   8
#define Nn   4096
#define Cc   768
#define Hh   8
#define HD   96
#define M1   (Bz * Nn)          // 32768 tokens
#define BH   (Bz * Hh)          // 64
#define ROWS (BH * HD)          // 6144 rows per tensor (q or k)
#define ACHUNK 8                // split-K chunks for attention gram

// ---------------------------------------------------------------------------
// Device scratch
// ---------------------------------------------------------------------------
__device__ __nv_bfloat16 g_qkvh[3ull * ROWS * Nn];   // attn path, bf16 hi
__device__ __nv_bfloat16 g_qkvl[3ull * ROWS * Nn];   // attn path, bf16 lo
__device__ float g_nsq[2 * ROWS * 32];
__device__ float g_inv[2 * ROWS];
__device__ float g_attn_part[(size_t)ACHUNK * BH * HD * HD];
__device__ float g_attn[(size_t)BH * HD * HD];
__device__ __half g_ctx_h[(size_t)M1 * Cc];          // ctx [m][c], fp16
__device__ __half g_x_h[(size_t)M1 * Cc];            // X fp16
__device__ __half g_wq_h[3 * Cc * Cc];               // W_qkv fp16
__device__ __half g_wp_h[Cc * Cc];                   // W_proj fp16

// ---------------------------------------------------------------------------
// PTX helpers (baseline target: mma.sync + ldmatrix + cp.async only)
// ---------------------------------------------------------------------------
#define LDSM4(R, A)                                                           \
    asm volatile("ldmatrix.sync.aligned.m8n8.x4.shared.b16 {%0,%1,%2,%3}, [%4];" \
        : "=r"((R)[0]), "=r"((R)[1]), "=r"((R)[2]), "=r"((R)[3]) : "r"(A))

#define LDSM4T(R, A)                                                          \
    asm volatile("ldmatrix.sync.aligned.m8n8.x4.trans.shared.b16 {%0,%1,%2,%3}, [%4];" \
        : "=r"((R)[0]), "=r"((R)[1]), "=r"((R)[2]), "=r"((R)[3]) : "r"(A))

#define MMA_BF(C, A, B0, B1)                                                  \
    asm volatile("mma.sync.aligned.m16n8k16.row.col.f32.bf16.bf16.f32 "       \
        "{%0,%1,%2,%3}, {%4,%5,%6,%7}, {%8,%9}, {%0,%1,%2,%3};"               \
        : "+f"((C)[0]), "+f"((C)[1]), "+f"((C)[2]), "+f"((C)[3])              \
        : "r"((A)[0]), "r"((A)[1]), "r"((A)[2]), "r"((A)[3]), "r"(B0), "r"(B1))

#define MMA_FP(C, A, B0, B1)                                                  \
    asm volatile("mma.sync.aligned.m16n8k16.row.col.f32.f16.f16.f32 "         \
        "{%0,%1,%2,%3}, {%4,%5,%6,%7}, {%8,%9}, {%0,%1,%2,%3};"               \
        : "+f"((C)[0]), "+f"((C)[1]), "+f"((C)[2]), "+f"((C)[3])              \
        : "r"((A)[0]), "r"((A)[1]), "r"((A)[2]), "r"((A)[3]), "r"(B0), "r"(B1))

#define CP16(d, s)                                                            \
    asm volatile("cp.async.cg.shared.global [%0], [%1], 16;" :: "r"(d), "l"(s))
#define CPCOMMIT() asm volatile("cp.async.commit_group;" ::: "memory")
#define CPWAIT2()  asm volatile("cp.async.wait_group 2;" ::: "memory")
#define CPWAIT1()  asm volatile("cp.async.wait_group 1;" ::: "memory")
#define CPWAIT0()  asm volatile("cp.async.wait_group 0;" ::: "memory")

__device__ __forceinline__ void split2bf(float x, float y, uint32_t& hi, uint32_t& lo) {
    __nv_bfloat16 hx = __float2bfloat16(x), hy = __float2bfloat16(y);
    __nv_bfloat16 lx = __float2bfloat16(x - __bfloat162float(hx));
    __nv_bfloat16 ly = __float2bfloat16(y - __bfloat162float(hy));
    hi = (uint32_t)__bfloat16_as_ushort(hx) | ((uint32_t)__bfloat16_as_ushort(hy) << 16);
    lo = (uint32_t)__bfloat16_as_ushort(lx) | ((uint32_t)__bfloat16_as_ushort(ly) << 16);
}

// Main GEMM smem pipeline (fp16 1-pass): tile = 128 rows x 64B swizzled = 8KB
// stage = 2 tiles (Ah, Bh) = 16KB ; 4 stages = 64KB (dynamic)
#define TILE_SZ  8192
#define STAGE_SZ 16384
#define SMEM_GEMM (4 * STAGE_SZ)   // 65536

// attn_part smem: tile = 96 rows x 48B = 4608B; stage = 4 tiles; 3 stages
#define AT_TILE  4608
#define AT_STAGE 18432
#define SMEM_ATT (3 * AT_STAGE)

// ctx smem layout: attn hi/lo tiles (96 x 208B) + v hi/lo tiles (96 x 272B)
#define CA_HI 0
#define CA_LO 19968
#define CV_HI 39936
#define CV_LO 66048
#define SMEM_CTX 92160

// ---------------------------------------------------------------------------
// Kernel 0: fp32 -> fp16 convert
// ---------------------------------------------------------------------------
__global__ __launch_bounds__(256) void cvt_h_kernel(
    const float* __restrict__ src, __half* __restrict__ dst, int n4) {
    int i = blockIdx.x * 256 + threadIdx.x;
    if (i < n4) {
        float4 v = ((const float4*)src)[i];
        ((__half2*)dst)[i * 2] = __floats2half2_rn(v.x, v.y);
        ((__half2*)dst)[i * 2 + 1] = __floats2half2_rn(v.z, v.w);
    }
}

// ---------------------------------------------------------------------------
// Main GEMM mainloop: 128x128 CTA tile, K-step 32, 4-stage cp.async,
// fp16 single pass: C = Ah*Bh.  8 warps (4M x 2N).
// SAFE pipeline order per iteration: wait -> __syncthreads -> fill -> commit
// -> consume.  (wait_group before the barrier is required: wait only covers
// the calling thread's copies; the barrier then publishes all threads'.)
// Swizzle: smem offset(r, chunk) = r*64 + ((chunk ^ ((r>>1)&3)) << 4)
// ---------------------------------------------------------------------------
struct GemmCtx {
    const __half *Ah, *Bh;    // row-major [*, Cc]
    size_t arow, brow;
};

__device__ __forceinline__ void gemm_mainloop(
    char* sm, const GemmCtx& g, float acc[2][8][4]) {
    const int tid = threadIdx.x, l = tid & 31, w = tid >> 5;
    const int wm = w & 3, wn = w >> 2;
    const uint32_t sb = (uint32_t)__cvta_generic_to_shared(sm);

    const int pr = tid >> 1, pc0 = (tid & 1) * 2;
    const int prx = (pr >> 1) & 3;
    const uint32_t po0 = (uint32_t)(pr * 64 + ((pc0 ^ prx) << 4));
    const uint32_t po1 = (uint32_t)(pr * 64 + (((pc0 + 1) ^ prx) << 4));
    const size_t asrc = (g.arow + pr) * Cc + pc0 * 8;
    const size_t bsrc = (g.brow + pr) * Cc + pc0 * 8;

    const int lr = l & 15, hsel = l >> 4;
    const int rowA = wm * 32 + lr, rowB = wn * 64 + lr;
    const int rxa = (rowA >> 1) & 3, rxb = (rowB >> 1) & 3;
    const uint32_t aswz[2] = { (uint32_t)((hsel ^ rxa) << 4),
                               (uint32_t)(((2 + hsel) ^ rxa) << 4) };
    const uint32_t bswz[2] = { (uint32_t)((hsel ^ rxb) << 4),
                               (uint32_t)(((2 + hsel) ^ rxb) << 4) };
    const uint32_t abase = (uint32_t)(rowA * 64);
    const uint32_t bbase = (uint32_t)(rowB * 64);

#pragma unroll
    for (int mt = 0; mt < 2; ++mt)
#pragma unroll
        for (int ni = 0; ni < 8; ++ni)
#pragma unroll
            for (int q = 0; q < 4; ++q) acc[mt][ni][q] = 0.f;

    const int NIT = Cc / 32;    // 24

#define G_FILL(DB, KT) do {                                                   \
        CP16((DB) + po0,           g.Ah + asrc + (KT));                       \
        CP16((DB) + po1,           g.Ah + asrc + (KT) + 8);                   \
        CP16((DB) + TILE_SZ + po0, g.Bh + bsrc + (KT));                       \
        CP16((DB) + TILE_SZ + po1, g.Bh + bsrc + (KT) + 8);                   \
    } while (0)

    // prologue: fill stages 0,1,2 (3 commit groups)
#pragma unroll
    for (int s = 0; s < 3; ++s) {
        G_FILL(sb + s * STAGE_SZ, s * 32);
        CPCOMMIT();
    }

    int buf = 0, fbuf = 3;
    for (int it = 0; it < NIT; ++it) {
        // commits so far = 3 + it ; wait_group 2 -> groups 0..it complete,
        // i.e. stage `it` has landed (this thread's share).
        CPWAIT2();
        __syncthreads();      // publish all threads' copies; also WAR-protect
                              // buffer fbuf (last read at iter it-1).
        if (it + 3 < NIT)
            G_FILL(sb + fbuf * STAGE_SZ, (it + 3) * 32);
        CPCOMMIT();

        const uint32_t tb = sb + buf * STAGE_SZ;
#pragma unroll
        for (int kk = 0; kk < 2; ++kk) {
            uint32_t ah[2][4], bh[4][4];
#pragma unroll
            for (int mt = 0; mt < 2; ++mt)
                LDSM4(ah[mt], tb + abase + mt * 1024 + aswz[kk]);
#pragma unroll
            for (int nt = 0; nt < 4; ++nt)
                LDSM4(bh[nt], tb + TILE_SZ + bbase + nt * 1024 + bswz[kk]);
#pragma unroll
            for (int mt = 0; mt < 2; ++mt)
#pragma unroll
                for (int nt = 0; nt < 4; ++nt)
#pragma unroll
                    for (int h = 0; h < 2; ++h)
                        MMA_FP(acc[mt][nt * 2 + h], ah[mt],
                               bh[nt][h], bh[nt][h + 2]);
        }
        buf = (buf + 1) & 3;
        fbuf = (fbuf + 1) & 3;
    }
    CPWAIT0();
    __syncthreads();
#undef G_FILL
}

// ---------------------------------------------------------------------------
// Kernel 1: QKV GEMM.  Epilogue scatters bf16 hi/lo into [t][bh][d][n] and
// emits per-(row, m-tile) sum-of-squares partials for q,k (norm fusion).
// ---------------------------------------------------------------------------
__global__ __launch_bounds__(256) void qkv_mma_kernel() {
    extern __shared__ __align__(128) char sm[];
    const int tid = threadIdx.x, l = tid & 31, w = tid >> 5;
    const int wm = w & 3, wn = w >> 2;
    const int j0 = blockIdx.x * 128, m0 = blockIdx.y * 128;

    GemmCtx g;
    g.Ah = g_x_h;  g.arow = (size_t)m0;
    g.Bh = g_wq_h; g.brow = (size_t)j0;

    float acc[2][8][4];
    gemm_mainloop(sm, g, acc);

    float* stage = (float*)sm;     // 64 x 132 floats
    const int b = m0 >> 12, nb = m0 & (Nn - 1);
#pragma unroll
    for (int c = 0; c < 2; ++c) {
        __syncthreads();
        if (wn == c) {
#pragma unroll
            for (int mt = 0; mt < 2; ++mt)
#pragma unroll
                for (int ni = 0; ni < 8; ++ni) {
                    int nt = ni >> 1, h = ni & 1;
                    int jl = nt * 16 + h * 8 + (l & 3) * 2;
                    int ml = wm * 32 + mt * 16 + (l >> 2);
                    const float* d = acc[mt][ni];
                    stage[jl * 132 + ml] = d[0];
                    stage[(jl + 1) * 132 + ml] = d[1];
                    stage[jl * 132 + ml + 8] = d[2];
                    stage[(jl + 1) * 132 + ml + 8] = d[3];
                }
        }
        __syncthreads();
        {
            int jl = tid >> 2, f4 = tid & 3;
            int j = j0 + c * 64 + jl;
            int t = j / Cc, r = j - t * Cc;
            size_t base = ((size_t)t * ROWS + b * Cc + r) * Nn + nb;
            float sq = 0.f;
#pragma unroll
            for (int i = 0; i < 8; ++i) {
                int idx = f4 + i * 4;
                float4 v = *(float4*)(stage + jl * 132 + idx * 4);
                sq = fmaf(v.x, v.x, sq); sq = fmaf(v.y, v.y, sq);
                sq = fmaf(v.z, v.z, sq); sq = fmaf(v.w, v.w, sq);
                uint2 h2, l2;
                split2bf(v.x, v.y, h2.x, l2.x);
                split2bf(v.z, v.w, h2.y, l2.y);
                *(uint2*)(g_qkvh + base + idx * 4) = h2;
                *(uint2*)(g_qkvl + base + idx * 4) = l2;
            }
            sq += __shfl_xor_sync(0xffffffffu, sq, 1);
            sq += __shfl_xor_sync(0xffffffffu, sq, 2);
            if (t < 2 && f4 == 0)
                g_nsq[((size_t)t * ROWS + b * Cc + r) * 32 + (nb >> 7)] = sq;
        }
    }
}

// ---------------------------------------------------------------------------
// Kernel 2: reduce norm partials -> inverse norms.  One warp per row.
// ---------------------------------------------------------------------------
__global__ __launch_bounds__(256) void nsq_reduce_kernel() {
    int row = blockIdx.x * 8 + (threadIdx.x >> 5);
    int lane = threadIdx.x & 31;
    float s = g_nsq[(size_t)row * 32 + lane];
#pragma unroll
    for (int o = 16; o; o >>= 1) s += __shfl_xor_sync(0xffffffffu, s, o);
    if (lane == 0)
        g_inv[row] = 1.0f / fmaxf(sqrtf(s), 1e-12f);
}

// ---------------------------------------------------------------------------
// Kernel 6: proj GEMM.  out = ctx @ Wp^T + bias, row-major epilogue.
// ---------------------------------------------------------------------------
__global__ __launch_bounds__(256) void proj_mma_kernel(
    const float* __restrict__ bias, float* __restrict__ out) {
    extern __shared__ __align__(128) char sm[];
    const int tid = threadIdx.x, l = tid & 31, w = tid >> 5;
    const int wm = w & 3, wn = w >> 2;
    const int j0 = blockIdx.x * 128, m0 = blockIdx.y * 128;

    GemmCtx g;
    g.Ah = g_ctx_h; g.arow = (size_t)m0;
    g.Bh = g_wp_h;  g.brow = (size_t)j0;

    float acc[2][8][4];
    gemm_mainloop(sm, g, acc);

    float* stage = (float*)sm;     // 128 x 68 floats
#pragma unroll
    for (int c = 0; c < 2; ++c) {
        __syncthreads();
        if (wn == c) {
#pragma unroll
            for (int mt = 0; mt < 2; ++mt)
#pragma unroll
                for (int ni = 0; ni < 8; ++ni) {
                    int nt = ni >> 1, h = ni & 1;
                    int jl = nt * 16 + h * 8 + (l & 3) * 2;
                    int ml = wm * 32 + mt * 16 + (l >> 2);
                    const float* d = acc[mt][ni];
                    stage[ml * 68 + jl] = d[0];
                    stage[ml * 68 + jl + 1] = d[1];
                    stage[(ml + 8) * 68 + jl] = d[2];
                    stage[(ml + 8) * 68 + jl + 1] = d[3];
                }
        }
        __syncthreads();
        {
            int ml = tid >> 1, half = tid & 1;
            int jb = j0 + c * 64 + half * 32;
#pragma unroll
            for (int i = 0; i < 8; ++i) {
                float4 v = *(float4*)(stage + ml * 68 + half * 32 + i * 4);
                float4 bb = *(const float4*)(bias + jb + i * 4);
                v.x += bb.x; v.y += bb.y; v.z += bb.z; v.w += bb.w;
                *(float4*)(out + (size_t)(m0 + ml) * Cc + jb + i * 4) = v;
            }
        }
    }
}

// ---------------------------------------------------------------------------
// Kernel 3: attention gram via HMMA (bf16 3-pass).  Safe pipeline order.
// ---------------------------------------------------------------------------
__global__ __launch_bounds__(192) void attn_part_kernel() {
    extern __shared__ __align__(128) char sm[];
    const int tid = threadIdx.x, l = tid & 31, wm = tid >> 5;   // wm 0..5
    const int bh = blockIdx.x, ch = blockIdx.y;
    const int n0 = ch * (Nn / ACHUNK);
    const uint32_t sb = (uint32_t)__cvta_generic_to_shared(sm);

    const int pr = tid % 96, pc = tid / 96;
    const uint32_t po = (uint32_t)(pr * 48 + pc * 16);
    const size_t qsrc = ((size_t)bh * HD + pr) * Nn + n0 + pc * 8;
    const size_t ksrc = ((size_t)ROWS + (size_t)bh * HD + pr) * Nn + n0 + pc * 8;

    const int lr = l & 15, hsel = l >> 4;
    const uint32_t aoff = (uint32_t)((wm * 16 + lr) * 48 + hsel * 16);
    const uint32_t boff = (uint32_t)(lr * 48 + hsel * 16);

    float acc[12][4];
#pragma unroll
    for (int i = 0; i < 12; ++i)
#pragma unroll
        for (int q = 0; q < 4; ++q) acc[i][q] = 0.f;

    const int NIT = (Nn / ACHUNK) / 16;    // 32

#define A_FILL(DB, KT) do {                                                   \
        CP16((DB) + po,               g_qkvh + qsrc + (KT));                  \
        CP16((DB) + AT_TILE + po,     g_qkvl + qsrc + (KT));                  \
        CP16((DB) + 2 * AT_TILE + po, g_qkvh + ksrc + (KT));                  \
        CP16((DB) + 3 * AT_TILE + po, g_qkvl + ksrc + (KT));                  \
    } while (0)

#pragma unroll
    for (int s = 0; s < 2; ++s) {
        A_FILL(sb + s * AT_STAGE, s * 16);
        CPCOMMIT();
    }

    int buf = 0, fbuf = 2;
    for (int it = 0; it < NIT; ++it) {
        // commits so far = 2 + it ; wait_group 1 -> stage `it` landed.
        CPWAIT1();
        __syncthreads();
        if (it + 2 < NIT)
            A_FILL(sb + fbuf * AT_STAGE, (it + 2) * 16);
        CPCOMMIT();

        const uint32_t tb = sb + buf * AT_STAGE;
        uint32_t ah[4], al[4], bhf[6][4], blf[6][4];
        LDSM4(ah, tb + aoff);
        LDSM4(al, tb + AT_TILE + aoff);
#pragma unroll
        for (int nt = 0; nt < 6; ++nt) {
            uint32_t o = boff + nt * (16 * 48);
            LDSM4(bhf[nt], tb + 2 * AT_TILE + o);
            LDSM4(blf[nt], tb + 3 * AT_TILE + o);
        }
#pragma unroll
        for (int p = 0; p < 3; ++p)
#pragma unroll
            for (int nt = 0; nt < 6; ++nt)
#pragma unroll
                for (int h = 0; h < 2; ++h) {
                    const uint32_t* A = (p == 2) ? al : ah;
                    const uint32_t* B = (p == 1) ? blf[nt] : bhf[nt];
                    MMA_BF(acc[nt * 2 + h], A, B[h], B[h + 2]);
                }
        buf = (buf == 2) ? 0 : buf + 1;
        fbuf = (fbuf == 2) ? 0 : fbuf + 1;
    }
    CPWAIT0();
#undef A_FILL

    float* op = g_attn_part + ((size_t)ch * BH + bh) * (HD * HD);
    const int r0 = wm * 16 + (l >> 2), cb = (l & 3) * 2;
#pragma unroll
    for (int nt = 0; nt < 6; ++nt)
#pragma unroll
        for (int h = 0; h < 2; ++h) {
            int col = nt * 16 + h * 8 + cb;
            const float* c = acc[nt * 2 + h];
            *(float2*)(op + r0 * HD + col) = make_float2(c[0], c[1]);
            *(float2*)(op + (r0 + 8) * HD + col) = make_float2(c[2], c[3]);
        }
}

// ---------------------------------------------------------------------------
// Kernel 4: reduce + scale + softmax
// ---------------------------------------------------------------------------
__global__ __launch_bounds__(128) void softmax_kernel(const float* __restrict__ temperature) {
    int row = blockIdx.x;
    int bh = row / HD;
    int h = bh & (Hh - 1);
    int tid = threadIdx.x;

    float v = -1e30f;
    if (tid < HD) {
        float s = 0.f;
#pragma unroll
        for (int c = 0; c < ACHUNK; ++c)
            s += g_attn_part[((size_t)c * ROWS + row) * HD + tid];
        s *= g_inv[row] * g_inv[ROWS + bh * HD + tid] * temperature[h];
        v = s;
    }
    __shared__ float red[4];
    float m = v;
#pragma unroll
    for (int o = 16; o; o >>= 1) m = fmaxf(m, __shfl_xor_sync(0xffffffffu, m, o));
    if ((tid & 31) == 0) red[tid >> 5] = m;
    __syncthreads();
    m = fmaxf(fmaxf(red[0], red[1]), fmaxf(red[2], red[3]));
    float e = (tid < HD) ? expf(v - m) : 0.f;
    __syncthreads();
    float s2 = e;
#pragma unroll
    for (int o = 16; o; o >>= 1) s2 += __shfl_xor_sync(0xffffffffu, s2, o);
    if ((tid & 31) == 0) red[tid >> 5] = s2;
    __syncthreads();
    float denom = red[0] + red[1] + red[2] + red[3];
    if (tid < HD) g_attn[(size_t)row * HD + tid] = e / denom;
}

// ---------------------------------------------------------------------------
// Kernel 5: ctx = attn @ v via HMMA (bf16 3-pass); emits fp16 ctx [m][c].
// ---------------------------------------------------------------------------
__global__ __launch_bounds__(192) void ctx_kernel() {
    extern __shared__ __align__(128) char sm[];
    const int tid = threadIdx.x, l = tid & 31, wm = tid >> 5;   // wm 0..5
    const int bh = blockIdx.x, n0 = blockIdx.y * 128;
    const uint32_t sb = (uint32_t)__cvta_generic_to_shared(sm);

    const size_t vbase = (2ull * ROWS + (size_t)bh * HD) * Nn + n0;
#pragma unroll
    for (int k = 0; k < 8; ++k) {
        int c = tid + k * 192;
        int r = c >> 4, chk = c & 15;
        uint32_t dst = sb + CV_HI + r * 272 + chk * 16;
        CP16(dst, g_qkvh + vbase + (size_t)r * Nn + chk * 8);
        CP16(dst + (CV_LO - CV_HI), g_qkvl + vbase + (size_t)r * Nn + chk * 8);
    }
    CPCOMMIT();

    {
        const float* ap = g_attn + (size_t)bh * HD * HD;
        __nv_bfloat16* Ahp = (__nv_bfloat16*)(sm + CA_HI);
        __nv_bfloat16* Alp = (__nv_bfloat16*)(sm + CA_LO);
        for (int i = tid; i < HD * HD; i += 192) {
            int d = i / HD, e = i - d * HD;
            float v = ap[i];
            __nv_bfloat16 hi = __float2bfloat16(v);
            __nv_bfloat16 lo = __float2bfloat16(v - __bfloat162float(hi));
            Ahp[d * 104 + e] = hi;
            Alp[d * 104 + e] = lo;
        }
    }
    CPWAIT0();
    __syncthreads();

    float acc[16][4];
#pragma unroll
    for (int i = 0; i < 16; ++i)
#pragma unroll
        for (int q = 0; q < 4; ++q) acc[i][q] = 0.f;

    const int lr = l & 15, hsel = l >> 4;
    const uint32_t aoff = sb + CA_HI + (uint32_t)((wm * 16 + lr) * 208 + hsel * 16);
    const int be = (l & 7) + ((l >> 4) << 3);
    const uint32_t boff = sb + CV_HI + (uint32_t)(be * 272 + ((l >> 3) & 1) * 16);

#pragma unroll
    for (int kc = 0; kc < 6; ++kc) {
        uint32_t ah[4], al[4];
        LDSM4(ah, aoff + kc * 32);
        LDSM4(al, aoff + (CA_LO - CA_HI) + kc * 32);
#pragma unroll
        for (int nq = 0; nq < 8; ++nq) {
            uint32_t bhf[4], blf[4];
            uint32_t o = boff + (uint32_t)(kc * 16 * 272 + nq * 32);
            LDSM4T(bhf, o);
            LDSM4T(blf, o + (CV_LO - CV_HI));
#pragma unroll
            for (int p = 0; p < 3; ++p)
#pragma unroll
                for (int h = 0; h < 2; ++h) {
                    const uint32_t* A = (p == 2) ? al : ah;
                    const uint32_t* B = (p == 1) ? blf : bhf;
                    MMA_BF(acc[nq * 2 + h], A, B[h], B[h + 2]);
                }
        }
    }

    __syncthreads();
    float* stage = (float*)sm;
    {
        const int d0 = wm * 16 + (l >> 2), cb = (l & 3) * 2;
#pragma unroll
        for (int nq = 0; nq < 8; ++nq)
#pragma unroll
            for (int h = 0; h < 2; ++h) {
                int n = nq * 16 + h * 8 + cb;
                const float* c = acc[nq * 2 + h];
                stage[n * 100 + d0] = c[0];
                stage[(n + 1) * 100 + d0] = c[1];
                stage[n * 100 + d0 + 8] = c[2];
                stage[(n + 1) * 100 + d0 + 8] = c[3];
            }
    }
    __syncthreads();
    {
        const int b = bh >> 3, hh = bh & 7;
#pragma unroll
        for (int k = 0; k < 32; ++k) {
            int flat = tid + k * 192;
            int n = flat / 48, j = flat - n * 48;
            float v0 = stage[n * 100 + j * 2];
            float v1 = stage[n * 100 + j * 2 + 1];
            size_t addr = ((size_t)(b * Nn + n0 + n)) * Cc + hh * HD + j * 2;
            *(__half2*)(g_ctx_h + addr) = __floats2half2_rn(v0, v1);
        }
    }
}

// ---------------------------------------------------------------------------
// Launcher
// ---------------------------------------------------------------------------
extern "C" void kernel_launch(void* const* d_in, const int* in_sizes, int n_in,
                              void* d_out, int out_size) {
    const float* x      = (const float*)d_in[0];
    const float* w_qkv  = (const float*)d_in[1];
    const float* temp   = (const float*)d_in[2];
    const float* w_proj = (const float*)d_in[3];
    const float* b_proj = (const float*)d_in[4];
    float* out = (float*)d_out;

    __half *xh, *qh, *ph;
    cudaGetSymbolAddress((void**)&xh, g_x_h);
    cudaGetSymbolAddress((void**)&qh, g_wq_h);
    cudaGetSymbolAddress((void**)&ph, g_wp_h);

    cudaFuncSetAttribute(qkv_mma_kernel,
                         cudaFuncAttributeMaxDynamicSharedMemorySize, SMEM_GEMM);
    cudaFuncSetAttribute(proj_mma_kernel,
                         cudaFuncAttributeMaxDynamicSharedMemorySize, SMEM_GEMM);
    cudaFuncSetAttribute(attn_part_kernel,
                         cudaFuncAttributeMaxDynamicSharedMemorySize, SMEM_ATT);
    cudaFuncSetAttribute(ctx_kernel,
                         cudaFuncAttributeMaxDynamicSharedMemorySize, SMEM_CTX);

    const int nx = M1 * Cc / 4, nq = 3 * Cc * Cc / 4, np = Cc * Cc / 4;
    cvt_h_kernel<<<(nx + 255) / 256, 256>>>(x, xh, nx);
    cvt_h_kernel<<<(nq + 255) / 256, 256>>>(w_qkv, qh, nq);
    cvt_h_kernel<<<(np + 255) / 256, 256>>>(w_proj, ph, np);

    qkv_mma_kernel<<<dim3(3 * Cc / 128, M1 / 128), 256, SMEM_GEMM>>>();
    nsq_reduce_kernel<<<2 * ROWS / 8, 256>>>();
    attn_part_kernel<<<dim3(BH, ACHUNK), 192, SMEM_ATT>>>();
    softmax_kernel<<<ROWS, 128>>>(temp);
    ctx_kernel<<<dim3(BH, Nn / 128), 192, SMEM_CTX>>>();
    proj_mma_kernel<<<dim3(Cc / 128, M1 / 128), 256, SMEM_GEMM>>>(b_proj, out);
}

// round 13
// speedup vs baseline: 3.0211x; 1.1192x over previous
#include <cuda_runtime.h>
#include <cuda_bf16.h>
#include <cuda_fp16.h>
#include <math.h>
#include <cstdint>

// Problem constants
#define Bz   8
#define Nn   4096
#define Cc   768
#define Hh   8
#define HD   96
#define M1   (Bz * Nn)          // 32768 tokens
#define BH   (Bz * Hh)          // 64
#define ROWS (BH * HD)          // 6144 rows per tensor (q or k)
#define ACHUNK 8                // split-K chunks for attention gram

// ---------------------------------------------------------------------------
// Device scratch
// ---------------------------------------------------------------------------
__device__ __half g_qkv[3ull * ROWS * Nn];           // attn path, fp16
__device__ float g_nsq[2 * ROWS * 32];
__device__ float g_inv[2 * ROWS];
__device__ float g_attn_part[(size_t)ACHUNK * BH * HD * HD];
__device__ float g_attn[(size_t)BH * HD * HD];
__device__ __half g_ctx_h[(size_t)M1 * Cc];          // ctx [m][c], fp16
__device__ __half g_x_h[(size_t)M1 * Cc];            // X fp16
__device__ __half g_wq_h[3 * Cc * Cc];               // W_qkv fp16
__device__ __half g_wp_h[Cc * Cc];                   // W_proj fp16

// ---------------------------------------------------------------------------
// PTX helpers (baseline target: mma.sync + ldmatrix + cp.async only)
// ---------------------------------------------------------------------------
#define LDSM4(R, A)                                                           \
    asm volatile("ldmatrix.sync.aligned.m8n8.x4.shared.b16 {%0,%1,%2,%3}, [%4];" \
        : "=r"((R)[0]), "=r"((R)[1]), "=r"((R)[2]), "=r"((R)[3]) : "r"(A))

#define LDSM4T(R, A)                                                          \
    asm volatile("ldmatrix.sync.aligned.m8n8.x4.trans.shared.b16 {%0,%1,%2,%3}, [%4];" \
        : "=r"((R)[0]), "=r"((R)[1]), "=r"((R)[2]), "=r"((R)[3]) : "r"(A))

#define MMA_FP(C, A, B0, B1)                                                  \
    asm volatile("mma.sync.aligned.m16n8k16.row.col.f32.f16.f16.f32 "         \
        "{%0,%1,%2,%3}, {%4,%5,%6,%7}, {%8,%9}, {%0,%1,%2,%3};"               \
        : "+f"((C)[0]), "+f"((C)[1]), "+f"((C)[2]), "+f"((C)[3])              \
        : "r"((A)[0]), "r"((A)[1]), "r"((A)[2]), "r"((A)[3]), "r"(B0), "r"(B1))

#define CP16(d, s)                                                            \
    asm volatile("cp.async.cg.shared.global [%0], [%1], 16;" :: "r"(d), "l"(s))
#define CPCOMMIT() asm volatile("cp.async.commit_group;" ::: "memory")
#define CPWAIT1()  asm volatile("cp.async.wait_group 1;" ::: "memory")
#define CPWAIT0()  asm volatile("cp.async.wait_group 0;" ::: "memory")

// Main GEMM (fp16 1-pass, KC=64): tile = 128 rows x 128B swizzled = 16KB
// stage = 2 tiles (A, B) = 32KB ; 3 stages = 96KB (dynamic), 2 CTAs/SM.
#define TILE_SZ  16384
#define STAGE_SZ 32768
#define SMEM_GEMM (3 * STAGE_SZ)   // 98304

// attn_part (fp16 1-pass, KC=32): tile = 96 rows x 64B swizzled = 6144B
// stage = 2 tiles (Q, K) = 12288B ; 3 stages = 36864B
#define QK_T     6144
#define AT_STAGE 12288
#define SMEM_ATT (3 * AT_STAGE)

// ctx smem: attn fp16 (96 x 208B) + v fp16 (96 x 272B); epilogue 128x100 fp32
#define CA_OFF 0
#define CV_OFF 19968
#define SMEM_CTX 51200

// ---------------------------------------------------------------------------
// Kernel 0: fp32 -> fp16 convert
// ---------------------------------------------------------------------------
__global__ __launch_bounds__(256) void cvt_h_kernel(
    const float* __restrict__ src, __half* __restrict__ dst, int n4) {
    int i = blockIdx.x * 256 + threadIdx.x;
    if (i < n4) {
        float4 v = ((const float4*)src)[i];
        ((__half2*)dst)[i * 2] = __floats2half2_rn(v.x, v.y);
        ((__half2*)dst)[i * 2 + 1] = __floats2half2_rn(v.z, v.w);
    }
}

// ---------------------------------------------------------------------------
// Main GEMM mainloop: 128x128 CTA tile, K-step 64, 3-stage cp.async,
// fp16 single pass.  8 warps (4M x 2N).  Safe order:
// wait -> __syncthreads -> fill -> commit -> consume.
// Swizzle (128B rows, 8 chunks): offset(r, c) = r*128 + ((c ^ (r&7)) << 4)
// ---------------------------------------------------------------------------
struct GemmCtx {
    const __half *Ah, *Bh;    // row-major [*, Cc]
    size_t arow, brow;
};

__device__ __forceinline__ void gemm_mainloop(
    char* sm, const GemmCtx& g, float acc[2][8][4]) {
    const int tid = threadIdx.x, l = tid & 31, w = tid >> 5;
    const int wm = w & 3, wn = w >> 2;
    const uint32_t sb = (uint32_t)__cvta_generic_to_shared(sm);

    // producer: row pr = tid>>1, chunks cb..cb+3 (16B each)
    const int pr = tid >> 1, cb = (tid & 1) * 4;
    const int prx = pr & 7;
    uint32_t po[4];
#pragma unroll
    for (int j = 0; j < 4; ++j)
        po[j] = (uint32_t)(pr * 128 + (((cb + j) ^ prx) << 4));
    const size_t asrc = (g.arow + pr) * Cc + cb * 8;
    const size_t bsrc = (g.brow + pr) * Cc + cb * 8;

    const int lr = l & 15, hsel = l >> 4;
    const int rowA = wm * 32 + lr, rowB = wn * 64 + lr;
    const int rxa = rowA & 7, rxb = rowB & 7;   // invariant under +16/+32
    uint32_t aswz[4], bswz[4];
#pragma unroll
    for (int kk = 0; kk < 4; ++kk) {
        aswz[kk] = (uint32_t)(((2 * kk + hsel) ^ rxa) << 4);
        bswz[kk] = (uint32_t)(((2 * kk + hsel) ^ rxb) << 4);
    }
    const uint32_t abase = (uint32_t)(rowA * 128);
    const uint32_t bbase = (uint32_t)(rowB * 128);

#pragma unroll
    for (int mt = 0; mt < 2; ++mt)
#pragma unroll
        for (int ni = 0; ni < 8; ++ni)
#pragma unroll
            for (int q = 0; q < 4; ++q) acc[mt][ni][q] = 0.f;

    const int NIT = Cc / 64;    // 12

#define G_FILL(DB, KT) do {                                                   \
        _Pragma("unroll")                                                     \
        for (int j = 0; j < 4; ++j) {                                         \
            CP16((DB) + po[j],           g.Ah + asrc + (KT) + j * 8);         \
            CP16((DB) + TILE_SZ + po[j], g.Bh + bsrc + (KT) + j * 8);         \
        }                                                                     \
    } while (0)

    // prologue: fill stages 0,1 (2 commit groups)
#pragma unroll
    for (int s = 0; s < 2; ++s) {
        G_FILL(sb + s * STAGE_SZ, s * 64);
        CPCOMMIT();
    }

    int buf = 0, fbuf = 2;
    for (int it = 0; it < NIT; ++it) {
        CPWAIT1();            // commits = 2+it ; stage `it` landed
        __syncthreads();      // publish all threads' copies; WAR-protect fbuf
        if (it + 2 < NIT)
            G_FILL(sb + fbuf * STAGE_SZ, (it + 2) * 64);
        CPCOMMIT();

        const uint32_t tb = sb + buf * STAGE_SZ;
#pragma unroll
        for (int kk = 0; kk < 4; ++kk) {
            uint32_t ah[2][4], bh[4][4];
#pragma unroll
            for (int mt = 0; mt < 2; ++mt)
                LDSM4(ah[mt], tb + abase + mt * 2048 + aswz[kk]);
#pragma unroll
            for (int nt = 0; nt < 4; ++nt)
                LDSM4(bh[nt], tb + TILE_SZ + bbase + nt * 2048 + bswz[kk]);
#pragma unroll
            for (int mt = 0; mt < 2; ++mt)
#pragma unroll
                for (int nt = 0; nt < 4; ++nt)
#pragma unroll
                    for (int h = 0; h < 2; ++h)
                        MMA_FP(acc[mt][nt * 2 + h], ah[mt],
                               bh[nt][h], bh[nt][h + 2]);
        }
        buf = (buf == 2) ? 0 : buf + 1;
        fbuf = (fbuf == 2) ? 0 : fbuf + 1;
    }
    CPWAIT0();
    __syncthreads();
#undef G_FILL
}

// ---------------------------------------------------------------------------
// Kernel 1: QKV GEMM.  Epilogue scatters fp16 into [t][bh][d][n] and emits
// per-(row, m-tile) sum-of-squares partials for q,k (norm fusion).
// ---------------------------------------------------------------------------
__global__ __launch_bounds__(256) void qkv_mma_kernel() {
    extern __shared__ __align__(128) char sm[];
    const int tid = threadIdx.x, l = tid & 31, w = tid >> 5;
    const int wm = w & 3, wn = w >> 2;
    const int j0 = blockIdx.x * 128, m0 = blockIdx.y * 128;

    GemmCtx g;
    g.Ah = g_x_h;  g.arow = (size_t)m0;
    g.Bh = g_wq_h; g.brow = (size_t)j0;

    float acc[2][8][4];
    gemm_mainloop(sm, g, acc);

    float* stage = (float*)sm;     // 64 x 132 floats
    const int b = m0 >> 12, nb = m0 & (Nn - 1);
#pragma unroll
    for (int c = 0; c < 2; ++c) {
        __syncthreads();
        if (wn == c) {
#pragma unroll
            for (int mt = 0; mt < 2; ++mt)
#pragma unroll
                for (int ni = 0; ni < 8; ++ni) {
                    int nt = ni >> 1, h = ni & 1;
                    int jl = nt * 16 + h * 8 + (l & 3) * 2;
                    int ml = wm * 32 + mt * 16 + (l >> 2);
                    const float* d = acc[mt][ni];
                    stage[jl * 132 + ml] = d[0];
                    stage[(jl + 1) * 132 + ml] = d[1];
                    stage[jl * 132 + ml + 8] = d[2];
                    stage[(jl + 1) * 132 + ml + 8] = d[3];
                }
        }
        __syncthreads();
        {
            int jl = tid >> 2, f4 = tid & 3;
            int j = j0 + c * 64 + jl;
            int t = j / Cc, r = j - t * Cc;
            size_t base = ((size_t)t * ROWS + b * Cc + r) * Nn + nb;
            float sq = 0.f;
#pragma unroll
            for (int i = 0; i < 8; ++i) {
                int idx = f4 + i * 4;
                float4 v = *(float4*)(stage + jl * 132 + idx * 4);
                sq = fmaf(v.x, v.x, sq); sq = fmaf(v.y, v.y, sq);
                sq = fmaf(v.z, v.z, sq); sq = fmaf(v.w, v.w, sq);
                __half2 h01 = __floats2half2_rn(v.x, v.y);
                __half2 h23 = __floats2half2_rn(v.z, v.w);
                uint2 u = make_uint2(*(uint32_t*)&h01, *(uint32_t*)&h23);
                *(uint2*)(g_qkv + base + idx * 4) = u;
            }
            sq += __shfl_xor_sync(0xffffffffu, sq, 1);
            sq += __shfl_xor_sync(0xffffffffu, sq, 2);
            if (t < 2 && f4 == 0)
                g_nsq[((size_t)t * ROWS + b * Cc + r) * 32 + (nb >> 7)] = sq;
        }
    }
}

// ---------------------------------------------------------------------------
// Kernel 2: reduce norm partials -> inverse norms.  One warp per row.
// ---------------------------------------------------------------------------
__global__ __launch_bounds__(256) void nsq_reduce_kernel() {
    int row = blockIdx.x * 8 + (threadIdx.x >> 5);
    int lane = threadIdx.x & 31;
    float s = g_nsq[(size_t)row * 32 + lane];
#pragma unroll
    for (int o = 16; o; o >>= 1) s += __shfl_xor_sync(0xffffffffu, s, o);
    if (lane == 0)
        g_inv[row] = 1.0f / fmaxf(sqrtf(s), 1e-12f);
}

// ---------------------------------------------------------------------------
// Kernel 6: proj GEMM.  out = ctx @ Wp^T + bias, row-major epilogue.
// ---------------------------------------------------------------------------
__global__ __launch_bounds__(256) void proj_mma_kernel(
    const float* __restrict__ bias, float* __restrict__ out) {
    extern __shared__ __align__(128) char sm[];
    const int tid = threadIdx.x, l = tid & 31, w = tid >> 5;
    const int wm = w & 3, wn = w >> 2;
    const int j0 = blockIdx.x * 128, m0 = blockIdx.y * 128;

    GemmCtx g;
    g.Ah = g_ctx_h; g.arow = (size_t)m0;
    g.Bh = g_wp_h;  g.brow = (size_t)j0;

    float acc[2][8][4];
    gemm_mainloop(sm, g, acc);

    float* stage = (float*)sm;     // 128 x 68 floats
#pragma unroll
    for (int c = 0; c < 2; ++c) {
        __syncthreads();
        if (wn == c) {
#pragma unroll
            for (int mt = 0; mt < 2; ++mt)
#pragma unroll
                for (int ni = 0; ni < 8; ++ni) {
                    int nt = ni >> 1, h = ni & 1;
                    int jl = nt * 16 + h * 8 + (l & 3) * 2;
                    int ml = wm * 32 + mt * 16 + (l >> 2);
                    const float* d = acc[mt][ni];
                    stage[ml * 68 + jl] = d[0];
                    stage[ml * 68 + jl + 1] = d[1];
                    stage[(ml + 8) * 68 + jl] = d[2];
                    stage[(ml + 8) * 68 + jl + 1] = d[3];
                }
        }
        __syncthreads();
        {
            int ml = tid >> 1, half = tid & 1;
            int jb = j0 + c * 64 + half * 32;
#pragma unroll
            for (int i = 0; i < 8; ++i) {
                float4 v = *(float4*)(stage + ml * 68 + half * 32 + i * 4);
                float4 bb = *(const float4*)(bias + jb + i * 4);
                v.x += bb.x; v.y += bb.y; v.z += bb.z; v.w += bb.w;
                *(float4*)(out + (size_t)(m0 + ml) * Cc + jb + i * 4) = v;
            }
        }
    }
}

// ---------------------------------------------------------------------------
// Kernel 3: attention gram via fp16 1-pass HMMA, KC=32.
// Block (bh, ch): 192 threads, 6 warps (one m16 band each), N=96.
// Swizzle (64B rows): offset(r, c) = r*64 + ((c ^ ((r>>1)&3)) << 4)
// ---------------------------------------------------------------------------
__global__ __launch_bounds__(192) void attn_part_kernel() {
    extern __shared__ __align__(128) char sm[];
    const int tid = threadIdx.x, l = tid & 31, wm = tid >> 5;   // wm 0..5
    const int bh = blockIdx.x, ch = blockIdx.y;
    const int n0 = ch * (Nn / ACHUNK);                          // chunk of 512
    const uint32_t sb = (uint32_t)__cvta_generic_to_shared(sm);

    const int pr = tid >> 1, pc0 = (tid & 1) * 2;               // pr 0..95
    const int prx = (pr >> 1) & 3;
    const uint32_t po0 = (uint32_t)(pr * 64 + ((pc0 ^ prx) << 4));
    const uint32_t po1 = (uint32_t)(pr * 64 + (((pc0 + 1) ^ prx) << 4));
    const size_t qsrc = ((size_t)bh * HD + pr) * Nn + n0 + pc0 * 8;
    const size_t ksrc = ((size_t)ROWS + (size_t)bh * HD + pr) * Nn + n0 + pc0 * 8;

    const int lr = l & 15, hsel = l >> 4;
    const int rowA = wm * 16 + lr;
    const int rxa = (rowA >> 1) & 3, rxb = (lr >> 1) & 3;
    const uint32_t aswz[2] = { (uint32_t)((hsel ^ rxa) << 4),
                               (uint32_t)(((2 + hsel) ^ rxa) << 4) };
    const uint32_t bswz[2] = { (uint32_t)((hsel ^ rxb) << 4),
                               (uint32_t)(((2 + hsel) ^ rxb) << 4) };
    const uint32_t abase = (uint32_t)(rowA * 64);
    const uint32_t bbase = (uint32_t)(lr * 64);

    float acc[12][4];
#pragma unroll
    for (int i = 0; i < 12; ++i)
#pragma unroll
        for (int q = 0; q < 4; ++q) acc[i][q] = 0.f;

    const int NIT = (Nn / ACHUNK) / 32;    // 16

#define A_FILL(DB, KT) do {                                                   \
        CP16((DB) + po0,        g_qkv + qsrc + (KT));                         \
        CP16((DB) + po1,        g_qkv + qsrc + (KT) + 8);                     \
        CP16((DB) + QK_T + po0, g_qkv + ksrc + (KT));                         \
        CP16((DB) + QK_T + po1, g_qkv + ksrc + (KT) + 8);                     \
    } while (0)

#pragma unroll
    for (int s = 0; s < 2; ++s) {
        A_FILL(sb + s * AT_STAGE, s * 32);
        CPCOMMIT();
    }

    int buf = 0, fbuf = 2;
    for (int it = 0; it < NIT; ++it) {
        CPWAIT1();
        __syncthreads();
        if (it + 2 < NIT)
            A_FILL(sb + fbuf * AT_STAGE, (it + 2) * 32);
        CPCOMMIT();

        const uint32_t tb = sb + buf * AT_STAGE;
#pragma unroll
        for (int kk = 0; kk < 2; ++kk) {
            uint32_t a[4], bf[6][4];
            LDSM4(a, tb + abase + aswz[kk]);
#pragma unroll
            for (int nt = 0; nt < 6; ++nt)
                LDSM4(bf[nt], tb + QK_T + bbase + nt * 1024 + bswz[kk]);
#pragma unroll
            for (int nt = 0; nt < 6; ++nt)
#pragma unroll
                for (int h = 0; h < 2; ++h)
                    MMA_FP(acc[nt * 2 + h], a, bf[nt][h], bf[nt][h + 2]);
        }
        buf = (buf == 2) ? 0 : buf + 1;
        fbuf = (fbuf == 2) ? 0 : fbuf + 1;
    }
    CPWAIT0();
#undef A_FILL

    float* op = g_attn_part + ((size_t)ch * BH + bh) * (HD * HD);
    const int r0 = wm * 16 + (l >> 2), cbn = (l & 3) * 2;
#pragma unroll
    for (int nt = 0; nt < 6; ++nt)
#pragma unroll
        for (int h = 0; h < 2; ++h) {
            int col = nt * 16 + h * 8 + cbn;
            const float* c = acc[nt * 2 + h];
            *(float2*)(op + r0 * HD + col) = make_float2(c[0], c[1]);
            *(float2*)(op + (r0 + 8) * HD + col) = make_float2(c[2], c[3]);
        }
}

// ---------------------------------------------------------------------------
// Kernel 4: reduce + scale + softmax
// ---------------------------------------------------------------------------
__global__ __launch_bounds__(128) void softmax_kernel(const float* __restrict__ temperature) {
    int row = blockIdx.x;
    int bh = row / HD;
    int h = bh & (Hh - 1);
    int tid = threadIdx.x;

    float v = -1e30f;
    if (tid < HD) {
        float s = 0.f;
#pragma unroll
        for (int c = 0; c < ACHUNK; ++c)
            s += g_attn_part[((size_t)c * ROWS + row) * HD + tid];
        s *= g_inv[row] * g_inv[ROWS + bh * HD + tid] * temperature[h];
        v = s;
    }
    __shared__ float red[4];
    float m = v;
#pragma unroll
    for (int o = 16; o; o >>= 1) m = fmaxf(m, __shfl_xor_sync(0xffffffffu, m, o));
    if ((tid & 31) == 0) red[tid >> 5] = m;
    __syncthreads();
    m = fmaxf(fmaxf(red[0], red[1]), fmaxf(red[2], red[3]));
    float e = (tid < HD) ? expf(v - m) : 0.f;
    __syncthreads();
    float s2 = e;
#pragma unroll
    for (int o = 16; o; o >>= 1) s2 += __shfl_xor_sync(0xffffffffu, s2, o);
    if ((tid & 31) == 0) red[tid >> 5] = s2;
    __syncthreads();
    float denom = red[0] + red[1] + red[2] + red[3];
    if (tid < HD) g_attn[(size_t)row * HD + tid] = e / denom;
}

// ---------------------------------------------------------------------------
// Kernel 5: ctx = attn @ v via fp16 1-pass HMMA; emits fp16 ctx [m][c].
// Block (bh, n-tile of 128): M=96 (d), N=128 (n), K=96 (e). 6 warps.
// attn fp16 [d][e] (208B-pad rows); v fp16 [e][n] (272B-pad rows, trans-B).
// ---------------------------------------------------------------------------
__global__ __launch_bounds__(192) void ctx_kernel() {
    extern __shared__ __align__(128) char sm[];
    const int tid = threadIdx.x, l = tid & 31, wm = tid >> 5;   // wm 0..5
    const int bh = blockIdx.x, n0 = blockIdx.y * 128;
    const uint32_t sb = (uint32_t)__cvta_generic_to_shared(sm);

    const size_t vbase = (2ull * ROWS + (size_t)bh * HD) * Nn + n0;
#pragma unroll
    for (int k = 0; k < 8; ++k) {
        int c = tid + k * 192;
        int r = c >> 4, chk = c & 15;
        CP16(sb + CV_OFF + r * 272 + chk * 16,
             g_qkv + vbase + (size_t)r * Nn + chk * 8);
    }
    CPCOMMIT();

    {
        const float* ap = g_attn + (size_t)bh * HD * HD;
        __half* Ap = (__half*)(sm + CA_OFF);
        for (int i = tid; i < HD * HD; i += 192) {
            int d = i / HD, e = i - d * HD;
            Ap[d * 104 + e] = __float2half_rn(ap[i]);
        }
    }
    CPWAIT0();
    __syncthreads();

    float acc[16][4];
#pragma unroll
    for (int i = 0; i < 16; ++i)
#pragma unroll
        for (int q = 0; q < 4; ++q) acc[i][q] = 0.f;

    const int lr = l & 15, hsel = l >> 4;
    const uint32_t aoff = sb + CA_OFF + (uint32_t)((wm * 16 + lr) * 208 + hsel * 16);
    const int be = (l & 7) + ((l >> 4) << 3);
    const uint32_t boff = sb + CV_OFF + (uint32_t)(be * 272 + ((l >> 3) & 1) * 16);

#pragma unroll
    for (int kc = 0; kc < 6; ++kc) {
        uint32_t a[4];
        LDSM4(a, aoff + kc * 32);
#pragma unroll
        for (int nq = 0; nq < 8; ++nq) {
            uint32_t bf[4];
            LDSM4T(bf, boff + (uint32_t)(kc * 16 * 272 + nq * 32));
#pragma unroll
            for (int h = 0; h < 2; ++h)
                MMA_FP(acc[nq * 2 + h], a, bf[h], bf[h + 2]);
        }
    }

    __syncthreads();
    float* stage = (float*)sm;
    {
        const int d0 = wm * 16 + (l >> 2), cbn = (l & 3) * 2;
#pragma unroll
        for (int nq = 0; nq < 8; ++nq)
#pragma unroll
            for (int h = 0; h < 2; ++h) {
                int n = nq * 16 + h * 8 + cbn;
                const float* c = acc[nq * 2 + h];
                stage[n * 100 + d0] = c[0];
                stage[(n + 1) * 100 + d0] = c[1];
                stage[n * 100 + d0 + 8] = c[2];
                stage[(n + 1) * 100 + d0 + 8] = c[3];
            }
    }
    __syncthreads();
    {
        const int b = bh >> 3, hh = bh & 7;
#pragma unroll
        for (int k = 0; k < 32; ++k) {
            int flat = tid + k * 192;
            int n = flat / 48, j = flat - n * 48;
            float v0 = stage[n * 100 + j * 2];
            float v1 = stage[n * 100 + j * 2 + 1];
            size_t addr = ((size_t)(b * Nn + n0 + n)) * Cc + hh * HD + j * 2;
            *(__half2*)(g_ctx_h + addr) = __floats2half2_rn(v0, v1);
        }
    }
}

// ---------------------------------------------------------------------------
// Launcher
// ---------------------------------------------------------------------------
extern "C" void kernel_launch(void* const* d_in, const int* in_sizes, int n_in,
                              void* d_out, int out_size) {
    const float* x      = (const float*)d_in[0];
    const float* w_qkv  = (const float*)d_in[1];
    const float* temp   = (const float*)d_in[2];
    const float* w_proj = (const float*)d_in[3];
    const float* b_proj = (const float*)d_in[4];
    float* out = (float*)d_out;

    __half *xh, *qh, *ph;
    cudaGetSymbolAddress((void**)&xh, g_x_h);
    cudaGetSymbolAddress((void**)&qh, g_wq_h);
    cudaGetSymbolAddress((void**)&ph, g_wp_h);

    cudaFuncSetAttribute(qkv_mma_kernel,
                         cudaFuncAttributeMaxDynamicSharedMemorySize, SMEM_GEMM);
    cudaFuncSetAttribute(proj_mma_kernel,
                         cudaFuncAttributeMaxDynamicSharedMemorySize, SMEM_GEMM);
    cudaFuncSetAttribute(attn_part_kernel,
                         cudaFuncAttributeMaxDynamicSharedMemorySize, SMEM_ATT);
    cudaFuncSetAttribute(ctx_kernel,
                         cudaFuncAttributeMaxDynamicSharedMemorySize, SMEM_CTX);

    const int nx = M1 * Cc / 4, nq = 3 * Cc * Cc / 4, np = Cc * Cc / 4;
    cvt_h_kernel<<<(nx + 255) / 256, 256>>>(x, xh, nx);
    cvt_h_kernel<<<(nq + 255) / 256, 256>>>(w_qkv, qh, nq);
    cvt_h_kernel<<<(np + 255) / 256, 256>>>(w_proj, ph, np);

    qkv_mma_kernel<<<dim3(3 * Cc / 128, M1 / 128), 256, SMEM_GEMM>>>();
    nsq_reduce_kernel<<<2 * ROWS / 8, 256>>>();
    attn_part_kernel<<<dim3(BH, ACHUNK), 192, SMEM_ATT>>>();
    softmax_kernel<<<ROWS, 128>>>(temp);
    ctx_kernel<<<dim3(BH, Nn / 128), 192, SMEM_CTX>>>();
    proj_mma_kernel<<<dim3(Cc / 128, M1 / 128), 256, SMEM_GEMM>>>(b_proj, out);
}